// round 12
// baseline (speedup 1.0000x reference)
#include <cuda_runtime.h>
#include <cuda_bf16.h>
#include <cuda_fp16.h>
#include <math.h>
#include <stdint.h>

// ---------------------------------------------------------------------------
// Static device scratch
// ---------------------------------------------------------------------------
__device__ float d_g0[5*12000];
__device__ __nv_bfloat16 d_h1h[12000*64];
__device__ __nv_bfloat16 d_h1l[12000*64];
__device__ float d_qk1[2*6*1504*256];           // q cols 0..127, k cols 128..255 (fp32)
__device__ __half d_v1[2*6*1504*512];           // v cols (o*4+m) in fp16
__device__ float d_o1raw[2*2*750*128];
__device__ float d_qkv2[2*2*754*96];            // v cols = 32+o*4+m
__device__ float d_out2[2*750*16];

__device__ __nv_bfloat16 d_W1bh[768*64];
__device__ __nv_bfloat16 d_W1bl[768*64];
__device__ float d_Wcat2[128*96];
__device__ float d_Weff0[5*64];
__device__ float d_emb1[4*10];
__device__ float d_emb2[4*10];
__device__ float d_C0;

// contiguous stats block, zeroed by k0 block 16:
// [0,30)=S0, [30,158)=sum1, [158,286)=sumsq1, [286,302)=sum2, [302,318)=sumsq2,
// [318]=k9 completion counter (as float bits, zeroed too)
__device__ float d_stats[319];
#define P_S0     (d_stats)
#define P_SUM1   (d_stats + 30)
#define P_SUMSQ1 (d_stats + 158)
#define P_SUM2   (d_stats + 286)
#define P_SUMSQ2 (d_stats + 302)
#define P_CTR    ((unsigned int*)(d_stats + 318))

__device__ __forceinline__ void mma_bf16(float4& c,
    uint32_t a0, uint32_t a1, uint32_t a2, uint32_t a3,
    uint32_t b0, uint32_t b1)
{
    asm volatile(
        "mma.sync.aligned.m16n8k16.row.col.f32.bf16.bf16.f32 "
        "{%0,%1,%2,%3},{%4,%5,%6,%7},{%8,%9},{%0,%1,%2,%3};"
        : "+f"(c.x), "+f"(c.y), "+f"(c.z), "+f"(c.w)
        : "r"(a0), "r"(a1), "r"(a2), "r"(a3), "r"(b0), "r"(b1));
}

__device__ __forceinline__ void ldsm_x4(uint32_t& r0, uint32_t& r1, uint32_t& r2, uint32_t& r3,
                                        uint32_t addr)
{
    asm volatile("ldmatrix.sync.aligned.m8n8.x4.shared.b16 {%0,%1,%2,%3}, [%4];"
        : "=r"(r0), "=r"(r1), "=r"(r2), "=r"(r3) : "r"(addr));
}

// ---------------------------------------------------------------------------
// K0: grid 17 blocks. Blocks 0..15: weight conversion. Block 16: embeddings,
//     Weff0, C0, stats+counter zeroing.
// ---------------------------------------------------------------------------
__global__ void k0_pre(const float* p0_q, const float* p0_k, const float* p0_v,
                       const float* p0_ea, const float* p0_eb, const float* p0_em,
                       const float* p1_q, const float* p1_k, const float* p1_v,
                       const float* p1_ea, const float* p1_eb, const float* p1_em,
                       const float* p2_q, const float* p2_k, const float* p2_v,
                       const float* p2_ea, const float* p2_eb, const float* p2_em)
{
    int t = threadIdx.x;
    int blk = blockIdx.x;

    if (blk < 16) {
        #pragma unroll
        for (int u = 0; u < 12; u++) {
            int idx = blk*3072 + u*256 + t;
            int j = idx / 64, c = idx % 64;
            float v;
            if (j < 128)       v = p1_q[c*128 + j];
            else if (j < 256)  v = p1_k[c*128 + (j-128)];
            else { int o = (j-256) >> 2, m = (j-256) & 3; v = p1_v[(m*64+c)*128 + o]; }
            __nv_bfloat16 hi = __float2bfloat16_rn(v);
            d_W1bh[idx] = hi;
            d_W1bl[idx] = __float2bfloat16_rn(v - __bfloat162float(hi));
        }
        #pragma unroll
        for (int u = 0; u < 3; u++) {
            int idx = blk*768 + u*256 + t;
            int c = idx / 96, j = idx % 96;
            float v;
            if (j < 16)       v = p2_q[c*16 + j];
            else if (j < 32)  v = p2_k[c*16 + (j-16)];
            else { int o = (j-32) >> 2, m = (j-32) & 3; v = p2_v[(m*128+c)*16 + o]; }
            d_Wcat2[idx] = v;
        }
        return;
    }

    // blk == 16: zero stats + counter + small precomputes
    for (int i = t; i < 319; i += 256) d_stats[i] = 0.f;

    __shared__ float logit0[4][5], logit1[4][10], logit2[4][10];
    __shared__ float emb0s[4][5];

    if (t == 0) {
        float s = 0.f;
        for (int o = 0; o < 64; o++) s += p0_q[o] * p0_k[o];
        d_C0 = s;
    }
    if (t >= 128 && t < 148) {
        int u = t - 128; int m = u / 5, j = u % 5;
        float la = 0.f, lb = 0.f;
        for (int o = 0; o < 64; o++) {
            la += p0_em[m*64+o] * p0_ea[o];
            lb += p0_em[m*64+o] * p0_eb[o*5+j];
        }
        logit0[m][j] = la + lb;
    }
    if (t < 40) {
        int m = t / 10, kl = t % 10, i = kl / 5, j = kl % 5;
        float la = 0.f, lb = 0.f;
        for (int o = 0; o < 128; o++) {
            la += p1_em[m*128+o] * p1_ea[o*2+i];
            lb += p1_em[m*128+o] * p1_eb[o*5+j];
        }
        logit1[m][kl] = la + lb;
    }
    if (t >= 64 && t < 104) {
        int u = t - 64; int m = u / 10, kl = u % 10, i = kl / 5, j = kl % 5;
        float la = 0.f, lb = 0.f;
        for (int o = 0; o < 16; o++) {
            la += p2_em[m*16+o] * p2_ea[o*2+i];
            lb += p2_em[m*16+o] * p2_eb[o*5+j];
        }
        logit2[m][kl] = la + lb;
    }
    __syncthreads();
    if (t < 5) {
        float mx = -1e30f;
        for (int m = 0; m < 4; m++) mx = fmaxf(mx, logit0[m][t]);
        float e[4], s = 0.f;
        for (int m = 0; m < 4; m++) { e[m] = __expf(logit0[m][t]-mx); s += e[m]; }
        for (int m = 0; m < 4; m++) emb0s[m][t] = e[m] / s;
    }
    if (t >= 32 && t < 42) {
        int kl = t - 32;
        float mx = -1e30f;
        for (int m = 0; m < 4; m++) mx = fmaxf(mx, logit1[m][kl]);
        float e[4], s = 0.f;
        for (int m = 0; m < 4; m++) { e[m] = __expf(logit1[m][kl]-mx); s += e[m]; }
        for (int m = 0; m < 4; m++) d_emb1[m*10+kl] = e[m] / s;
    }
    if (t >= 64 && t < 74) {
        int kl = t - 64;
        float mx = -1e30f;
        for (int m = 0; m < 4; m++) mx = fmaxf(mx, logit2[m][kl]);
        float e[4], s = 0.f;
        for (int m = 0; m < 4; m++) { e[m] = __expf(logit2[m][kl]-mx); s += e[m]; }
        for (int m = 0; m < 4; m++) d_emb2[m*10+kl] = e[m] / s;
    }
    __syncthreads();
    for (int idx = t; idx < 5*64; idx += blockDim.x) {
        int l = idx / 64, o = idx % 64;
        float s = 0.f;
        for (int m = 0; m < 4; m++) s += emb0s[m][l] * p0_v[m*64+o];
        d_Weff0[idx] = s;
    }
}

// ---------------------------------------------------------------------------
// K1: stage0 attention -> g[5] + low-rank BN stats; also zero-fills the
// hp=0 pad rows of d_qk1/d_v1 (consumed by k5 after k4). grid (24,8,2), 128
// ---------------------------------------------------------------------------
__global__ void k1_stem0(const float* x)
{
    int tid = threadIdx.x;
    int w = blockIdx.x * 128 + tid;
    int h = blockIdx.y, b = blockIdx.z;
    bool valid = (w < 3000);

    // pad zero-fill: 192512 float4 (qk) + 192512 uint4 (v) over 384 blocks
    {
        int blockId = (blockIdx.z * 8 + blockIdx.y) * 24 + blockIdx.x;
        #pragma unroll
        for (int u = 0; u < 4; u++) {
            int idx = (blockId * 4 + u) * 128 + tid;
            if (idx < 192512) {
                int fidx = idx * 4;
                int row = fidx >> 8, col = fidx & 255;
                int bb = row >= 1504; int wp = row - bb*1504;
                *(float4*)&d_qk1[((size_t)(bb*9024 + wp))*256 + col] =
                    make_float4(0.f,0.f,0.f,0.f);
                int eidx = idx * 8;
                int vrow = eidx >> 9, vcol = eidx & 511;
                int b2 = vrow >= 1504; int wp2 = vrow - b2*1504;
                *(uint4*)&d_v1[((size_t)(b2*9024 + wp2))*512 + vcol] =
                    make_uint4(0,0,0,0);
            }
        }
    }

    float g[5] = {0.f,0.f,0.f,0.f,0.f};
    if (valid) {
        const float* xr = x + (b*8 + h) * 3000;
        float xc = xr[w];
        float C0 = d_C0;
        float xl[5], sc[5];
        float mx = -1e30f;
        #pragma unroll
        for (int l = 0; l < 5; l++) {
            int c = w + l - 2;
            xl[l] = (c >= 0 && c < 3000) ? xr[c] : 0.f;
            sc[l] = xc * xl[l] * C0;
            mx = fmaxf(mx, sc[l]);
        }
        float s = 0.f;
        #pragma unroll
        for (int l = 0; l < 5; l++) { sc[l] = __expf(sc[l]-mx); s += sc[l]; }
        float inv = 1.f / s;
        #pragma unroll
        for (int l = 0; l < 5; l++) g[l] = sc[l] * inv * xl[l];
    }

    float st[20];
    {
        int si = 0;
        #pragma unroll
        for (int l = 0; l < 5; l++) st[si++] = g[l];
        #pragma unroll
        for (int l = 0; l < 5; l++)
            #pragma unroll
            for (int l2 = l; l2 < 5; l2++) st[si++] = g[l]*g[l2];
    }
    #pragma unroll
    for (int i = 0; i < 20; i++)
        #pragma unroll
        for (int off = 16; off; off >>= 1)
            st[i] += __shfl_xor_sync(0xffffffffu, st[i], off);

    __shared__ float red[4][20];
    int lane = tid & 31, wrp = tid >> 5;
    if (lane == 0)
        for (int i = 0; i < 20; i++) red[wrp][i] = st[i];
    __syncthreads();
    if (tid < 20) {
        float v = red[0][tid] + red[1][tid] + red[2][tid] + red[3][tid];
        int slot;
        if (tid < 5) slot = tid;
        else {
            int k = tid - 5, l = 0;
            while (k >= 5 - l) { k -= 5 - l; l++; }
            slot = 5 + l*5 + (l + k);
        }
        atomicAdd(&P_S0[slot], v);
    }

    if (valid && !(h & 1) && !(w & 1)) {
        int p = b*6000 + (h>>1)*1500 + (w>>1);
        #pragma unroll
        for (int l = 0; l < 5; l++) d_g0[l*12000 + p] = g[l];
    }
}

// ---------------------------------------------------------------------------
// K3: stage0 BN + ReLU -> h1 bf16 hi/lo. grid 3000, block 256
// ---------------------------------------------------------------------------
__global__ void k3_h1(const float* g0, const float* b0)
{
    __shared__ float sW[5*64];
    __shared__ float sScale[64], sShift[64];
    int tid = threadIdx.x;
    for (int i = tid; i < 320; i += 256) sW[i] = d_Weff0[i];
    __syncthreads();
    if (tid < 64) {
        int c = tid;
        float Wc[5];
        #pragma unroll
        for (int l = 0; l < 5; l++) Wc[l] = sW[l*64 + c];
        float mn = 0.f, mq = 0.f;
        #pragma unroll
        for (int l = 0; l < 5; l++) {
            mn += P_S0[l] * Wc[l];
            #pragma unroll
            for (int l2 = 0; l2 < 5; l2++) {
                int lo = l < l2 ? l : l2, hi = l < l2 ? l2 : l;
                mq += P_S0[5 + lo*5 + hi] * Wc[l] * Wc[l2];
            }
        }
        float n = 48000.f;
        float mean = mn / n;
        float var  = mq / n - mean*mean;
        float sc = g0[c] * rsqrtf(var + 1e-5f);
        sScale[c] = sc;
        sShift[c] = b0[c] - mean * sc;
    }
    __syncthreads();

    int c = tid & 63;
    int p = blockIdx.x * 4 + (tid >> 6);
    float a = 0.f;
    #pragma unroll
    for (int l = 0; l < 5; l++) a += d_g0[l*12000 + p] * sW[l*64 + c];
    float y = fmaxf(fmaf(a, sScale[c], sShift[c]), 0.f);
    __nv_bfloat16 hi = __float2bfloat16_rn(y);
    d_h1h[p*64 + c] = hi;
    d_h1l[p*64 + c] = __float2bfloat16_rn(y - __bfloat162float(hi));
}

// ---------------------------------------------------------------------------
// K4: stage1 qkv GEMM (real rows only, M'=12032), bf16 3-term + ldmatrix,
// 4x2 warp layout. q/k fp32, v fp16. grid (94, 12), block 256.
// ---------------------------------------------------------------------------
#define K4_SMEM ((128*72 + 128*72 + 64*72 + 64*72) * 2)

__global__ void __launch_bounds__(256) k4_gemm1()
{
    extern __shared__ __nv_bfloat16 sh[];
    __nv_bfloat16* Ah = sh;
    __nv_bfloat16* Al = Ah + 128*72;
    __nv_bfloat16* Bh = Al + 128*72;
    __nv_bfloat16* Bl = Bh + 64*72;

    int tid = threadIdx.x;
    int rowBase = blockIdx.x * 128;
    int colBase = blockIdx.y * 64;

    {
        int r = tid >> 1;
        int half = (tid & 1) * 32;
        int prow = rowBase + r;
        int b = prow / 6016; int rem = prow % 6016;
        int hp = 1 + rem / 1504; int wp = rem % 1504;
        bool valid = (wp >= 2 && wp < 1502);
        __nv_bfloat16* dh = Ah + r*72 + half;
        __nv_bfloat16* dl = Al + r*72 + half;
        if (valid) {
            int pos = ((b*4 + (hp-1))*1500 + (wp-2))*64 + half;
            const uint4* sH = (const uint4*)(d_h1h + pos);
            const uint4* sL = (const uint4*)(d_h1l + pos);
            #pragma unroll
            for (int u = 0; u < 4; u++) {
                ((uint4*)dh)[u] = sH[u];
                ((uint4*)dl)[u] = sL[u];
            }
        } else {
            uint4 z = make_uint4(0,0,0,0);
            #pragma unroll
            for (int u = 0; u < 4; u++) { ((uint4*)dh)[u] = z; ((uint4*)dl)[u] = z; }
        }
    }
    {
        int n = tid >> 2;
        int seg = (tid & 3) * 16;
        const uint4* sH = (const uint4*)(d_W1bh + (colBase + n)*64 + seg);
        const uint4* sL = (const uint4*)(d_W1bl + (colBase + n)*64 + seg);
        uint4* dh = (uint4*)(Bh + n*72 + seg);
        uint4* dl = (uint4*)(Bl + n*72 + seg);
        dh[0] = sH[0]; dh[1] = sH[1];
        dl[0] = sL[0]; dl[1] = sL[1];
    }
    __syncthreads();

    int lane = tid & 31, wid = tid >> 5;
    int g = lane >> 2, tg = lane & 3;
    int mr   = (wid >> 1) * 32;
    int ncol = (wid & 1) * 32;

    int arow = (lane < 16) ? lane : (lane - 16);
    int acol = (lane < 16) ? 0 : 8;
    uint32_t aAddrH[2], aAddrL[2];
    #pragma unroll
    for (int mt = 0; mt < 2; mt++) {
        aAddrH[mt] = (uint32_t)__cvta_generic_to_shared(Ah + (mr + mt*16 + arow)*72 + acol);
        aAddrL[mt] = (uint32_t)__cvta_generic_to_shared(Al + (mr + mt*16 + arow)*72 + acol);
    }
    int brow = (lane & 7) + ((lane >> 4) << 3);
    int bcol = ((lane >> 3) & 1) * 8;
    uint32_t bAddrH[2], bAddrL[2];
    #pragma unroll
    for (int pr = 0; pr < 2; pr++) {
        bAddrH[pr] = (uint32_t)__cvta_generic_to_shared(Bh + (ncol + pr*16 + brow)*72 + bcol);
        bAddrL[pr] = (uint32_t)__cvta_generic_to_shared(Bl + (ncol + pr*16 + brow)*72 + bcol);
    }

    float4 acc[2][4];
    #pragma unroll
    for (int i = 0; i < 2; i++)
        #pragma unroll
        for (int j = 0; j < 4; j++) acc[i][j] = make_float4(0.f,0.f,0.f,0.f);

    #pragma unroll
    for (int ks = 0; ks < 4; ks++) {
        uint32_t koff = ks * 32;
        uint32_t ah[2][4], al[2][4], bh[2][4], bl[2][4];
        #pragma unroll
        for (int mt = 0; mt < 2; mt++) {
            ldsm_x4(ah[mt][0],ah[mt][1],ah[mt][2],ah[mt][3], aAddrH[mt] + koff);
            ldsm_x4(al[mt][0],al[mt][1],al[mt][2],al[mt][3], aAddrL[mt] + koff);
        }
        #pragma unroll
        for (int pr = 0; pr < 2; pr++) {
            ldsm_x4(bh[pr][0],bh[pr][1],bh[pr][2],bh[pr][3], bAddrH[pr] + koff);
            ldsm_x4(bl[pr][0],bl[pr][1],bl[pr][2],bl[pr][3], bAddrL[pr] + koff);
        }
        #pragma unroll
        for (int mt = 0; mt < 2; mt++)
            #pragma unroll
            for (int pr = 0; pr < 2; pr++) {
                mma_bf16(acc[mt][2*pr  ], ah[mt][0],ah[mt][1],ah[mt][2],ah[mt][3], bh[pr][0],bh[pr][1]);
                mma_bf16(acc[mt][2*pr  ], ah[mt][0],ah[mt][1],ah[mt][2],ah[mt][3], bl[pr][0],bl[pr][1]);
                mma_bf16(acc[mt][2*pr  ], al[mt][0],al[mt][1],al[mt][2],al[mt][3], bh[pr][0],bh[pr][1]);
                mma_bf16(acc[mt][2*pr+1], ah[mt][0],ah[mt][1],ah[mt][2],ah[mt][3], bh[pr][2],bh[pr][3]);
                mma_bf16(acc[mt][2*pr+1], ah[mt][0],ah[mt][1],ah[mt][2],ah[mt][3], bl[pr][2],bl[pr][3]);
                mma_bf16(acc[mt][2*pr+1], al[mt][0],al[mt][1],al[mt][2],al[mt][3], bh[pr][2],bh[pr][3]);
            }
    }

    bool isQK = (colBase < 256);
    #pragma unroll
    for (int mt = 0; mt < 2; mt++) {
        #pragma unroll
        for (int half = 0; half < 2; half++) {
            int prow = rowBase + mr + mt*16 + half*8 + g;
            int b = prow / 6016; int rem = prow % 6016;
            int hp = 1 + rem / 1504; int wp = rem % 1504;
            size_t orow = (size_t)(b*6 + hp)*1504 + wp;
            #pragma unroll
            for (int j = 0; j < 4; j++) {
                int col = colBase + ncol + j*8 + tg*2;
                float2 v = half ? make_float2(acc[mt][j].z, acc[mt][j].w)
                                : make_float2(acc[mt][j].x, acc[mt][j].y);
                if (isQK) {
                    *(float2*)&d_qk1[orow*256 + col] = v;
                } else {
                    __half2 hv;
                    hv.x = __float2half_rn(v.x);
                    hv.y = __float2half_rn(v.y);
                    *(__half2*)&d_v1[orow*512 + (col - 256)] = hv;
                }
            }
        }
    }
}

// ---------------------------------------------------------------------------
// K5: stage1 attention combine, smem-staged q(fp32)/k(fp32)/v(fp16) window.
// 10 positions/block, 512 threads. grid (150, 4, 2).
// ---------------------------------------------------------------------------
#define K5_SMEM ((10*128 + 28*128) * 4 + 28*512*2)

__global__ void k5_attn1()
{
    extern __shared__ float sm5[];
    float* sq = sm5;                               // [10][128]
    float* sk = sm5 + 10*128;                      // [28][128]
    __half* sv = (__half*)(sm5 + 10*128 + 28*128); // [28][512]

    int w0 = blockIdx.x * 10, h = blockIdx.y, b = blockIdx.z;
    int tid = threadIdx.x, lane = tid & 31, wrp = tid >> 5;  // 16 warps
    __shared__ float ssc[10][10];
    __shared__ float cm4[10][40];

    const float* qkbase = d_qk1 + (size_t)b * 6 * 1504 * 256;
    const __half* vbase = d_v1 + (size_t)b * 6 * 1504 * 512;

    for (int idx = tid; idx < 320; idx += 512) {
        int p = idx >> 5, c4 = idx & 31;
        ((float4*)sq)[p*32 + c4] =
            *(const float4*)(qkbase + ((h+1)*1504 + (w0+2+p))*256 + c4*4);
    }
    for (int idx = tid; idx < 896; idx += 512) {
        int r = idx >> 5, c4 = idx & 31;
        int i = r / 14, jj = r % 14;
        ((float4*)(sk + r*128))[c4] =
            *(const float4*)(qkbase + ((h+i)*1504 + (w0+jj))*256 + 128 + c4*4);
    }
    for (int idx = tid; idx < 1792; idx += 512) {
        int r = idx >> 6, c4 = idx & 63;
        int i = r / 14, jj = r % 14;
        ((uint4*)(sv + r*512))[c4] =
            *(const uint4*)(vbase + ((h+i)*1504 + (w0+jj))*512 + c4*8);
    }
    __syncthreads();

    for (int pair = wrp; pair < 100; pair += 16) {
        int p = pair / 10, kl = pair % 10;
        int i = kl / 5, j = kl % 5;
        float4 q4 = ((const float4*)(sq + p*128))[lane];
        float4 k4 = ((const float4*)(sk + (i*14 + p + j)*128))[lane];
        float s = q4.x*k4.x + q4.y*k4.y + q4.z*k4.z + q4.w*k4.w;
        #pragma unroll
        for (int off = 16; off; off >>= 1) s += __shfl_xor_sync(0xffffffffu, s, off);
        if (lane == 0) ssc[p][kl] = s;
    }
    __syncthreads();
    if (tid < 10) {
        float mx = -1e30f;
        #pragma unroll
        for (int kl = 0; kl < 10; kl++) mx = fmaxf(mx, ssc[tid][kl]);
        float e[10], s = 0.f;
        #pragma unroll
        for (int kl = 0; kl < 10; kl++) { e[kl] = __expf(ssc[tid][kl]-mx); s += e[kl]; }
        float inv = 1.f / s;
        #pragma unroll
        for (int kl = 0; kl < 10; kl++) {
            float a = e[kl] * inv;
            #pragma unroll
            for (int m = 0; m < 4; m++) cm4[tid][kl*4+m] = a * d_emb1[m*10+kl];
        }
    }
    __syncthreads();

    int o = tid & 127;
    int ph = tid >> 7;
    float s1 = 0.f, s2 = 0.f;
    for (int p = ph; p < 10; p += 4) {
        const float* cw = cm4[p];
        float acc = 0.f;
        #pragma unroll
        for (int kl = 0; kl < 10; kl++) {
            int i = kl / 5, j = kl % 5;
            uint2 pv = *(const uint2*)(sv + (i*14 + p + j)*512 + o*4);
            float2 v01 = __half22float2(*(const __half2*)&pv.x);
            float2 v23 = __half22float2(*(const __half2*)&pv.y);
            acc += cw[kl*4]*v01.x + cw[kl*4+1]*v01.y + cw[kl*4+2]*v23.x + cw[kl*4+3]*v23.y;
        }
        s1 += acc; s2 += acc*acc;
        if (!(h & 1) && !((w0+p) & 1))
            d_o1raw[((b*2 + (h>>1))*750 + ((w0+p)>>1))*128 + o] = acc;
    }
    atomicAdd(&P_SUM1[o], s1);
    atomicAdd(&P_SUMSQ1[o], s2);
}

// ---------------------------------------------------------------------------
// K8: stage2 qkv GEMM, ILP-split dots, 8 positions/block.
// grid (95, 2, 2), block 256.
// ---------------------------------------------------------------------------
#define K8_SMEM ((128*96 + 8*128) * 4)

__global__ void k8_gemm2(const float* g1, const float* b1)
{
    extern __shared__ float sm8[];
    float* sWt = sm8;               // [128][96]
    float* sa  = sm8 + 128*96;      // [8][128]
    __shared__ float sScale[128], sShift[128];

    int t = threadIdx.x;
    int hp = blockIdx.y, b = blockIdx.z;
    int W0 = blockIdx.x * 8;

    if (t < 128) {
        float n = 12000.f;
        float mean = P_SUM1[t] / n;
        float var  = P_SUMSQ1[t] / n - mean*mean;
        float sc = g1[t] * rsqrtf(var + 1e-5f);
        sScale[t] = sc;
        sShift[t] = b1[t] - mean*sc;
    }
    for (int idx = t; idx < 3072; idx += 256)
        ((float4*)sWt)[idx] = ((const float4*)d_Wcat2)[idx];
    __syncthreads();

    for (int idx = t; idx < 1024; idx += 256) {
        int ps = idx >> 7, i = idx & 127;
        int wp = W0 + ps;
        float v = 0.f;
        if (wp >= 2 && wp < 752) {
            float raw = d_o1raw[(((b*2 + hp)*750) + (wp-2))*128 + i];
            v = fmaxf(fmaf(raw, sScale[i], sShift[i]), 0.f);
        }
        sa[ps*128 + i] = v;
    }
    __syncthreads();

    #pragma unroll
    for (int k = 0; k < 3; k++) {
        int pair = t + k*256;
        int ps = pair / 96, o = pair - (pair/96)*96;
        int wp = W0 + ps;
        if (wp >= 754) continue;
        const float* av = sa + ps*128;
        float a0 = 0.f, a1 = 0.f, a2 = 0.f, a3 = 0.f;
        #pragma unroll
        for (int c = 0; c < 32; c++) {
            a0 = fmaf(av[c],     sWt[c*96 + o],        a0);
            a1 = fmaf(av[c+32],  sWt[(c+32)*96 + o],   a1);
            a2 = fmaf(av[c+64],  sWt[(c+64)*96 + o],   a2);
            a3 = fmaf(av[c+96],  sWt[(c+96)*96 + o],   a3);
        }
        d_qkv2[(((b*2 + hp)*754) + wp)*96 + o] = (a0 + a1) + (a2 + a3);
    }
}

// ---------------------------------------------------------------------------
// K9: stage2 attention combine, warp per position; last block also runs the
// stage2 BN + ReLU + AvgPool finale. grid (188, 2), block 128.
// ---------------------------------------------------------------------------
__global__ void k9_attn2(float* out, const float* g2, const float* b2)
{
    __shared__ float semb[40];
    int tid = threadIdx.x;
    if (tid < 40) { int kl = tid >> 2, m = tid & 3; semb[tid] = d_emb2[m*10+kl]; }
    __syncthreads();

    int lane = tid & 31, wrp = tid >> 5;
    int w = blockIdx.x * 4 + wrp, b = blockIdx.y;

    if (w < 750) {
        const float* base = d_qkv2 + (size_t)b * 2 * 754 * 96;
        const float* qp = base + (w + 2) * 96;
        float qv = (lane < 16) ? qp[lane] : 0.f;

        float scl[10];
        float mx = -1e30f;
        #pragma unroll
        for (int kl = 0; kl < 10; kl++) {
            int i = kl / 5, j = kl % 5;
            const float* kp = base + (i*754 + (w+j))*96 + 16;
            float pr = (lane < 16) ? qv * kp[lane] : 0.f;
            #pragma unroll
            for (int off = 8; off; off >>= 1) pr += __shfl_xor_sync(0xffffffffu, pr, off);
            scl[kl] = pr;
            mx = fmaxf(mx, pr);
        }
        float s = 0.f;
        #pragma unroll
        for (int kl = 0; kl < 10; kl++) { scl[kl] = __expf(scl[kl]-mx); s += scl[kl]; }
        float inv = 1.f / s;
        if (lane < 16) {
            float acc = 0.f;
            #pragma unroll
            for (int kl = 0; kl < 10; kl++) {
                int i = kl / 5, j = kl % 5;
                float4 v = *(const float4*)(base + (i*754 + (w+j))*96 + 32 + lane*4);
                float aw = scl[kl] * inv;
                acc += aw * (semb[kl*4]*v.x + semb[kl*4+1]*v.y + semb[kl*4+2]*v.z + semb[kl*4+3]*v.w);
            }
            d_out2[(b*750 + w)*16 + lane] = acc;
            atomicAdd(&P_SUM2[lane], acc);
            atomicAdd(&P_SUMSQ2[lane], acc*acc);
        }
    }

    // ---- last-block finale (k11 fused) ----
    __threadfence();
    __syncthreads();
    __shared__ unsigned int sIsLast;
    if (tid == 0) sIsLast = (atomicAdd(P_CTR, 1u) == 375u) ? 1u : 0u;
    __syncthreads();
    if (!sIsLast) return;

    __shared__ float sSc[16], sSf[16];
    if (tid < 16) {
        float nn = 1500.f;
        float mean = P_SUM2[tid] / nn;
        float var  = P_SUMSQ2[tid] / nn - mean*mean;
        float sc = g2[tid] * rsqrtf(var + 1e-5f);
        sSc[tid] = sc;
        sSf[tid] = b2[tid] - mean * sc;
    }
    __syncthreads();

    // 416 outputs: (b2,c,n). 128 threads -> warp per (b,n) chunk.
    // Each thread handles outputs strided; inner 56-sum serial per output.
    for (int oidx = tid; oidx < 416; oidx += 128) {
        int bb = oidx / 208;
        int rem = oidx % 208;
        int c = rem / 13, n = rem % 13;
        float s = 0.f;
        #pragma unroll 8
        for (int u = 0; u < 56; u++) {
            float raw = d_out2[(bb*750 + n*56 + u)*16 + c];
            s += fmaxf(fmaf(raw, sSc[c], sSf[c]), 0.f);
        }
        out[(bb*16 + c)*13 + n] = s * (1.f/56.f);
    }
}

// ---------------------------------------------------------------------------
extern "C" void kernel_launch(void* const* d_in, const int* in_sizes, int n_in,
                              void* d_out, int out_size)
{
    const float* x     = (const float*)d_in[0];
    const float* p0_q  = (const float*)d_in[1];
    const float* p0_k  = (const float*)d_in[2];
    const float* p0_v  = (const float*)d_in[3];
    const float* p0_ea = (const float*)d_in[4];
    const float* p0_eb = (const float*)d_in[5];
    const float* p0_em = (const float*)d_in[6];
    const float* p0_g  = (const float*)d_in[7];
    const float* p0_b  = (const float*)d_in[8];
    const float* p1_q  = (const float*)d_in[9];
    const float* p1_k  = (const float*)d_in[10];
    const float* p1_v  = (const float*)d_in[11];
    const float* p1_ea = (const float*)d_in[12];
    const float* p1_eb = (const float*)d_in[13];
    const float* p1_em = (const float*)d_in[14];
    const float* p1_g  = (const float*)d_in[15];
    const float* p1_b  = (const float*)d_in[16];
    const float* p2_q  = (const float*)d_in[17];
    const float* p2_k  = (const float*)d_in[18];
    const float* p2_v  = (const float*)d_in[19];
    const float* p2_ea = (const float*)d_in[20];
    const float* p2_eb = (const float*)d_in[21];
    const float* p2_em = (const float*)d_in[22];
    const float* p2_g  = (const float*)d_in[23];
    const float* p2_b  = (const float*)d_in[24];
    float* out = (float*)d_out;

    static int smem_set = 0;
    if (!smem_set) {
        cudaFuncSetAttribute(k4_gemm1, cudaFuncAttributeMaxDynamicSharedMemorySize, K4_SMEM);
        cudaFuncSetAttribute(k4_gemm1, cudaFuncAttributePreferredSharedMemoryCarveout,
                             cudaSharedmemCarveoutMaxShared);
        cudaFuncSetAttribute(k5_attn1, cudaFuncAttributeMaxDynamicSharedMemorySize, K5_SMEM);
        cudaFuncSetAttribute(k5_attn1, cudaFuncAttributePreferredSharedMemoryCarveout,
                             cudaSharedmemCarveoutMaxShared);
        cudaFuncSetAttribute(k8_gemm2, cudaFuncAttributeMaxDynamicSharedMemorySize, K8_SMEM);
        smem_set = 1;
    }

    k0_pre<<<17, 256>>>(p0_q, p0_k, p0_v, p0_ea, p0_eb, p0_em,
                        p1_q, p1_k, p1_v, p1_ea, p1_eb, p1_em,
                        p2_q, p2_k, p2_v, p2_ea, p2_eb, p2_em);
    k1_stem0<<<dim3(24, 8, 2), 128>>>(x);
    k3_h1<<<3000, 256>>>(p0_g, p0_b);
    k4_gemm1<<<dim3(94, 12), 256, K4_SMEM>>>();
    k5_attn1<<<dim3(150, 4, 2), 512, K5_SMEM>>>();
    k8_gemm2<<<dim3(95, 2, 2), 256, K8_SMEM>>>(p1_g, p1_b);
    k9_attn2<<<dim3(188, 2), 128>>>(out, p2_g, p2_b);
}

// round 13
// speedup vs baseline: 1.0907x; 1.0907x over previous
#include <cuda_runtime.h>
#include <cuda_bf16.h>
#include <cuda_fp16.h>
#include <math.h>
#include <stdint.h>

// ---------------------------------------------------------------------------
// Static device scratch
// ---------------------------------------------------------------------------
__device__ float d_g0[5*12000];
__device__ __nv_bfloat16 d_h1h[12000*64];
__device__ __nv_bfloat16 d_h1l[12000*64];
__device__ float d_qk1[2*6*1504*256];           // q cols 0..127, k cols 128..255 (fp32)
__device__ __half d_v1[2*6*1504*512];           // v cols (o*4+m) in fp16
__device__ float d_o1raw[2*2*750*128];
__device__ float d_qkv2[2*2*754*96];            // v cols = 32+o*4+m
__device__ float d_out2[2*750*16];

__device__ __nv_bfloat16 d_W1bh[768*64];
__device__ __nv_bfloat16 d_W1bl[768*64];
__device__ float d_Wcat2[128*96];
__device__ float d_Weff0[5*64];
__device__ float d_emb1[4*10];
__device__ float d_emb2[4*10];
__device__ float d_C0;

// contiguous stats block, zeroed by k0 block 16:
// [0,30)=S0, [30,158)=sum1, [158,286)=sumsq1, [286,302)=sum2, [302,318)=sumsq2
__device__ float d_stats[318];
#define P_S0     (d_stats)
#define P_SUM1   (d_stats + 30)
#define P_SUMSQ1 (d_stats + 158)
#define P_SUM2   (d_stats + 286)
#define P_SUMSQ2 (d_stats + 302)

__device__ __forceinline__ void mma_bf16(float4& c,
    uint32_t a0, uint32_t a1, uint32_t a2, uint32_t a3,
    uint32_t b0, uint32_t b1)
{
    asm volatile(
        "mma.sync.aligned.m16n8k16.row.col.f32.bf16.bf16.f32 "
        "{%0,%1,%2,%3},{%4,%5,%6,%7},{%8,%9},{%0,%1,%2,%3};"
        : "+f"(c.x), "+f"(c.y), "+f"(c.z), "+f"(c.w)
        : "r"(a0), "r"(a1), "r"(a2), "r"(a3), "r"(b0), "r"(b1));
}

__device__ __forceinline__ void ldsm_x4(uint32_t& r0, uint32_t& r1, uint32_t& r2, uint32_t& r3,
                                        uint32_t addr)
{
    asm volatile("ldmatrix.sync.aligned.m8n8.x4.shared.b16 {%0,%1,%2,%3}, [%4];"
        : "=r"(r0), "=r"(r1), "=r"(r2), "=r"(r3) : "r"(addr));
}

// ---------------------------------------------------------------------------
// K0: grid 17 blocks. Blocks 0..15: weight conversion. Block 16: embeddings,
//     Weff0, C0, stats zeroing.
// ---------------------------------------------------------------------------
__global__ void k0_pre(const float* p0_q, const float* p0_k, const float* p0_v,
                       const float* p0_ea, const float* p0_eb, const float* p0_em,
                       const float* p1_q, const float* p1_k, const float* p1_v,
                       const float* p1_ea, const float* p1_eb, const float* p1_em,
                       const float* p2_q, const float* p2_k, const float* p2_v,
                       const float* p2_ea, const float* p2_eb, const float* p2_em)
{
    int t = threadIdx.x;
    int blk = blockIdx.x;

    if (blk < 16) {
        #pragma unroll
        for (int u = 0; u < 12; u++) {
            int idx = blk*3072 + u*256 + t;
            int j = idx / 64, c = idx % 64;
            float v;
            if (j < 128)       v = p1_q[c*128 + j];
            else if (j < 256)  v = p1_k[c*128 + (j-128)];
            else { int o = (j-256) >> 2, m = (j-256) & 3; v = p1_v[(m*64+c)*128 + o]; }
            __nv_bfloat16 hi = __float2bfloat16_rn(v);
            d_W1bh[idx] = hi;
            d_W1bl[idx] = __float2bfloat16_rn(v - __bfloat162float(hi));
        }
        #pragma unroll
        for (int u = 0; u < 3; u++) {
            int idx = blk*768 + u*256 + t;
            int c = idx / 96, j = idx % 96;
            float v;
            if (j < 16)       v = p2_q[c*16 + j];
            else if (j < 32)  v = p2_k[c*16 + (j-16)];
            else { int o = (j-32) >> 2, m = (j-32) & 3; v = p2_v[(m*128+c)*16 + o]; }
            d_Wcat2[idx] = v;
        }
        return;
    }

    // blk == 16: zero stats + small precomputes
    for (int i = t; i < 318; i += 256) d_stats[i] = 0.f;

    __shared__ float logit0[4][5], logit1[4][10], logit2[4][10];
    __shared__ float emb0s[4][5];

    if (t == 0) {
        float s = 0.f;
        for (int o = 0; o < 64; o++) s += p0_q[o] * p0_k[o];
        d_C0 = s;
    }
    if (t >= 128 && t < 148) {
        int u = t - 128; int m = u / 5, j = u % 5;
        float la = 0.f, lb = 0.f;
        for (int o = 0; o < 64; o++) {
            la += p0_em[m*64+o] * p0_ea[o];
            lb += p0_em[m*64+o] * p0_eb[o*5+j];
        }
        logit0[m][j] = la + lb;
    }
    if (t < 40) {
        int m = t / 10, kl = t % 10, i = kl / 5, j = kl % 5;
        float la = 0.f, lb = 0.f;
        for (int o = 0; o < 128; o++) {
            la += p1_em[m*128+o] * p1_ea[o*2+i];
            lb += p1_em[m*128+o] * p1_eb[o*5+j];
        }
        logit1[m][kl] = la + lb;
    }
    if (t >= 64 && t < 104) {
        int u = t - 64; int m = u / 10, kl = u % 10, i = kl / 5, j = kl % 5;
        float la = 0.f, lb = 0.f;
        for (int o = 0; o < 16; o++) {
            la += p2_em[m*16+o] * p2_ea[o*2+i];
            lb += p2_em[m*16+o] * p2_eb[o*5+j];
        }
        logit2[m][kl] = la + lb;
    }
    __syncthreads();
    if (t < 5) {
        float mx = -1e30f;
        for (int m = 0; m < 4; m++) mx = fmaxf(mx, logit0[m][t]);
        float e[4], s = 0.f;
        for (int m = 0; m < 4; m++) { e[m] = __expf(logit0[m][t]-mx); s += e[m]; }
        for (int m = 0; m < 4; m++) emb0s[m][t] = e[m] / s;
    }
    if (t >= 32 && t < 42) {
        int kl = t - 32;
        float mx = -1e30f;
        for (int m = 0; m < 4; m++) mx = fmaxf(mx, logit1[m][kl]);
        float e[4], s = 0.f;
        for (int m = 0; m < 4; m++) { e[m] = __expf(logit1[m][kl]-mx); s += e[m]; }
        for (int m = 0; m < 4; m++) d_emb1[m*10+kl] = e[m] / s;
    }
    if (t >= 64 && t < 74) {
        int kl = t - 64;
        float mx = -1e30f;
        for (int m = 0; m < 4; m++) mx = fmaxf(mx, logit2[m][kl]);
        float e[4], s = 0.f;
        for (int m = 0; m < 4; m++) { e[m] = __expf(logit2[m][kl]-mx); s += e[m]; }
        for (int m = 0; m < 4; m++) d_emb2[m*10+kl] = e[m] / s;
    }
    __syncthreads();
    for (int idx = t; idx < 5*64; idx += blockDim.x) {
        int l = idx / 64, o = idx % 64;
        float s = 0.f;
        for (int m = 0; m < 4; m++) s += emb0s[m][l] * p0_v[m*64+o];
        d_Weff0[idx] = s;
    }
}

// ---------------------------------------------------------------------------
// K1: stage0 attention -> g[5] + low-rank BN stats; also zero-fills the
// hp=0 pad rows of d_qk1/d_v1. grid (24,8,2), block 128
// ---------------------------------------------------------------------------
__global__ void k1_stem0(const float* x)
{
    int tid = threadIdx.x;
    int w = blockIdx.x * 128 + tid;
    int h = blockIdx.y, b = blockIdx.z;
    bool valid = (w < 3000);

    // pad zero-fill: 192512 float4 (qk) + 192512 uint4 (v) over 384 blocks
    {
        int blockId = (blockIdx.z * 8 + blockIdx.y) * 24 + blockIdx.x;
        #pragma unroll
        for (int u = 0; u < 4; u++) {
            int idx = (blockId * 4 + u) * 128 + tid;
            if (idx < 192512) {
                int fidx = idx * 4;
                int row = fidx >> 8, col = fidx & 255;
                int bb = row >= 1504; int wp = row - bb*1504;
                *(float4*)&d_qk1[((size_t)(bb*9024 + wp))*256 + col] =
                    make_float4(0.f,0.f,0.f,0.f);
                int eidx = idx * 8;
                int vrow = eidx >> 9, vcol = eidx & 511;
                int b2 = vrow >= 1504; int wp2 = vrow - b2*1504;
                *(uint4*)&d_v1[((size_t)(b2*9024 + wp2))*512 + vcol] =
                    make_uint4(0,0,0,0);
            }
        }
    }

    float g[5] = {0.f,0.f,0.f,0.f,0.f};
    if (valid) {
        const float* xr = x + (b*8 + h) * 3000;
        float xc = xr[w];
        float C0 = d_C0;
        float xl[5], sc[5];
        float mx = -1e30f;
        #pragma unroll
        for (int l = 0; l < 5; l++) {
            int c = w + l - 2;
            xl[l] = (c >= 0 && c < 3000) ? xr[c] : 0.f;
            sc[l] = xc * xl[l] * C0;
            mx = fmaxf(mx, sc[l]);
        }
        float s = 0.f;
        #pragma unroll
        for (int l = 0; l < 5; l++) { sc[l] = __expf(sc[l]-mx); s += sc[l]; }
        float inv = 1.f / s;
        #pragma unroll
        for (int l = 0; l < 5; l++) g[l] = sc[l] * inv * xl[l];
    }

    float st[20];
    {
        int si = 0;
        #pragma unroll
        for (int l = 0; l < 5; l++) st[si++] = g[l];
        #pragma unroll
        for (int l = 0; l < 5; l++)
            #pragma unroll
            for (int l2 = l; l2 < 5; l2++) st[si++] = g[l]*g[l2];
    }
    #pragma unroll
    for (int i = 0; i < 20; i++)
        #pragma unroll
        for (int off = 16; off; off >>= 1)
            st[i] += __shfl_xor_sync(0xffffffffu, st[i], off);

    __shared__ float red[4][20];
    int lane = tid & 31, wrp = tid >> 5;
    if (lane == 0)
        for (int i = 0; i < 20; i++) red[wrp][i] = st[i];
    __syncthreads();
    if (tid < 20) {
        float v = red[0][tid] + red[1][tid] + red[2][tid] + red[3][tid];
        int slot;
        if (tid < 5) slot = tid;
        else {
            int k = tid - 5, l = 0;
            while (k >= 5 - l) { k -= 5 - l; l++; }
            slot = 5 + l*5 + (l + k);
        }
        atomicAdd(&P_S0[slot], v);
    }

    if (valid && !(h & 1) && !(w & 1)) {
        int p = b*6000 + (h>>1)*1500 + (w>>1);
        #pragma unroll
        for (int l = 0; l < 5; l++) d_g0[l*12000 + p] = g[l];
    }
}

// ---------------------------------------------------------------------------
// K3: stage0 BN + ReLU -> h1 bf16 hi/lo. grid 3000, block 256
// ---------------------------------------------------------------------------
__global__ void k3_h1(const float* g0, const float* b0)
{
    __shared__ float sW[5*64];
    __shared__ float sScale[64], sShift[64];
    int tid = threadIdx.x;
    for (int i = tid; i < 320; i += 256) sW[i] = d_Weff0[i];
    __syncthreads();
    if (tid < 64) {
        int c = tid;
        float Wc[5];
        #pragma unroll
        for (int l = 0; l < 5; l++) Wc[l] = sW[l*64 + c];
        float mn = 0.f, mq = 0.f;
        #pragma unroll
        for (int l = 0; l < 5; l++) {
            mn += P_S0[l] * Wc[l];
            #pragma unroll
            for (int l2 = 0; l2 < 5; l2++) {
                int lo = l < l2 ? l : l2, hi = l < l2 ? l2 : l;
                mq += P_S0[5 + lo*5 + hi] * Wc[l] * Wc[l2];
            }
        }
        float n = 48000.f;
        float mean = mn / n;
        float var  = mq / n - mean*mean;
        float sc = g0[c] * rsqrtf(var + 1e-5f);
        sScale[c] = sc;
        sShift[c] = b0[c] - mean * sc;
    }
    __syncthreads();

    int c = tid & 63;
    int p = blockIdx.x * 4 + (tid >> 6);
    float a = 0.f;
    #pragma unroll
    for (int l = 0; l < 5; l++) a += d_g0[l*12000 + p] * sW[l*64 + c];
    float y = fmaxf(fmaf(a, sScale[c], sShift[c]), 0.f);
    __nv_bfloat16 hi = __float2bfloat16_rn(y);
    d_h1h[p*64 + c] = hi;
    d_h1l[p*64 + c] = __float2bfloat16_rn(y - __bfloat162float(hi));
}

// ---------------------------------------------------------------------------
// K4: stage1 qkv GEMM (real rows, M'=12032), bf16 3-term + ldmatrix.
// BM=128, BN=128, 4x2 warp layout (Mw=32, Nw=64). q/k fp32, v fp16.
// grid (94, 6), block 256.
// ---------------------------------------------------------------------------
#define K4_SMEM ((128*72 + 128*72 + 128*72 + 128*72) * 2)

__global__ void __launch_bounds__(256) k4_gemm1()
{
    extern __shared__ __nv_bfloat16 sh[];
    __nv_bfloat16* Ah = sh;               // [128][72]
    __nv_bfloat16* Al = Ah + 128*72;
    __nv_bfloat16* Bh = Al + 128*72;      // [128 n][72 k]
    __nv_bfloat16* Bl = Bh + 128*72;

    int tid = threadIdx.x;
    int rowBase = blockIdx.x * 128;
    int colBase = blockIdx.y * 128;

    // A tile staging
    {
        int r = tid >> 1;
        int half = (tid & 1) * 32;
        int prow = rowBase + r;
        int b = prow / 6016; int rem = prow % 6016;
        int hp = 1 + rem / 1504; int wp = rem % 1504;
        bool valid = (wp >= 2 && wp < 1502);
        __nv_bfloat16* dh = Ah + r*72 + half;
        __nv_bfloat16* dl = Al + r*72 + half;
        if (valid) {
            int pos = ((b*4 + (hp-1))*1500 + (wp-2))*64 + half;
            const uint4* sH = (const uint4*)(d_h1h + pos);
            const uint4* sL = (const uint4*)(d_h1l + pos);
            #pragma unroll
            for (int u = 0; u < 4; u++) {
                ((uint4*)dh)[u] = sH[u];
                ((uint4*)dl)[u] = sL[u];
            }
        } else {
            uint4 z = make_uint4(0,0,0,0);
            #pragma unroll
            for (int u = 0; u < 4; u++) { ((uint4*)dh)[u] = z; ((uint4*)dl)[u] = z; }
        }
    }
    // B tile staging: 128 n rows x 64 k, hi+lo. 2 threads/row, 4 uint4 each.
    {
        int n = tid >> 1;
        int seg = (tid & 1) * 32;
        const uint4* sH = (const uint4*)(d_W1bh + (colBase + n)*64 + seg);
        const uint4* sL = (const uint4*)(d_W1bl + (colBase + n)*64 + seg);
        uint4* dh = (uint4*)(Bh + n*72 + seg);
        uint4* dl = (uint4*)(Bl + n*72 + seg);
        #pragma unroll
        for (int u = 0; u < 4; u++) { dh[u] = sH[u]; dl[u] = sL[u]; }
    }
    __syncthreads();

    int lane = tid & 31, wid = tid >> 5;
    int g = lane >> 2, tg = lane & 3;
    int mr   = (wid >> 1) * 32;       // 4 M-groups of 32
    int ncol = (wid & 1) * 64;        // 2 N-halves of 64

    int arow = (lane < 16) ? lane : (lane - 16);
    int acol = (lane < 16) ? 0 : 8;
    uint32_t aAddrH[2], aAddrL[2];
    #pragma unroll
    for (int mt = 0; mt < 2; mt++) {
        aAddrH[mt] = (uint32_t)__cvta_generic_to_shared(Ah + (mr + mt*16 + arow)*72 + acol);
        aAddrL[mt] = (uint32_t)__cvta_generic_to_shared(Al + (mr + mt*16 + arow)*72 + acol);
    }
    int brow = (lane & 7) + ((lane >> 4) << 3);
    int bcol = ((lane >> 3) & 1) * 8;
    uint32_t bAddrH[4], bAddrL[4];
    #pragma unroll
    for (int pr = 0; pr < 4; pr++) {
        bAddrH[pr] = (uint32_t)__cvta_generic_to_shared(Bh + (ncol + pr*16 + brow)*72 + bcol);
        bAddrL[pr] = (uint32_t)__cvta_generic_to_shared(Bl + (ncol + pr*16 + brow)*72 + bcol);
    }

    float4 acc[2][8];
    #pragma unroll
    for (int i = 0; i < 2; i++)
        #pragma unroll
        for (int j = 0; j < 8; j++) acc[i][j] = make_float4(0.f,0.f,0.f,0.f);

    #pragma unroll
    for (int ks = 0; ks < 4; ks++) {
        uint32_t koff = ks * 32;
        uint32_t ah[2][4], al[2][4];
        #pragma unroll
        for (int mt = 0; mt < 2; mt++) {
            ldsm_x4(ah[mt][0],ah[mt][1],ah[mt][2],ah[mt][3], aAddrH[mt] + koff);
            ldsm_x4(al[mt][0],al[mt][1],al[mt][2],al[mt][3], aAddrL[mt] + koff);
        }
        #pragma unroll
        for (int pr = 0; pr < 4; pr++) {
            uint32_t bh0,bh1,bh2,bh3, bl0,bl1,bl2,bl3;
            ldsm_x4(bh0,bh1,bh2,bh3, bAddrH[pr] + koff);
            ldsm_x4(bl0,bl1,bl2,bl3, bAddrL[pr] + koff);
            #pragma unroll
            for (int mt = 0; mt < 2; mt++) {
                mma_bf16(acc[mt][2*pr  ], ah[mt][0],ah[mt][1],ah[mt][2],ah[mt][3], bh0,bh1);
                mma_bf16(acc[mt][2*pr  ], ah[mt][0],ah[mt][1],ah[mt][2],ah[mt][3], bl0,bl1);
                mma_bf16(acc[mt][2*pr  ], al[mt][0],al[mt][1],al[mt][2],al[mt][3], bh0,bh1);
                mma_bf16(acc[mt][2*pr+1], ah[mt][0],ah[mt][1],ah[mt][2],ah[mt][3], bh2,bh3);
                mma_bf16(acc[mt][2*pr+1], ah[mt][0],ah[mt][1],ah[mt][2],ah[mt][3], bl2,bl3);
                mma_bf16(acc[mt][2*pr+1], al[mt][0],al[mt][1],al[mt][2],al[mt][3], bh2,bh3);
            }
        }
    }

    bool isQK = (colBase < 256);
    #pragma unroll
    for (int mt = 0; mt < 2; mt++) {
        #pragma unroll
        for (int half = 0; half < 2; half++) {
            int prow = rowBase + mr + mt*16 + half*8 + g;
            int b = prow / 6016; int rem = prow % 6016;
            int hp = 1 + rem / 1504; int wp = rem % 1504;
            size_t orow = (size_t)(b*6 + hp)*1504 + wp;
            #pragma unroll
            for (int j = 0; j < 8; j++) {
                int col = colBase + ncol + j*8 + tg*2;
                float2 v = half ? make_float2(acc[mt][j].z, acc[mt][j].w)
                                : make_float2(acc[mt][j].x, acc[mt][j].y);
                if (isQK) {
                    *(float2*)&d_qk1[orow*256 + col] = v;
                } else {
                    __half2 hv;
                    hv.x = __float2half_rn(v.x);
                    hv.y = __float2half_rn(v.y);
                    *(__half2*)&d_v1[orow*512 + (col - 256)] = hv;
                }
            }
        }
    }
}

// ---------------------------------------------------------------------------
// K5: stage1 attention combine, smem-staged q(fp32)/k(fp32)/v(fp16) window.
// 10 positions/block, 512 threads. grid (150, 4, 2).
// ---------------------------------------------------------------------------
#define K5_SMEM ((10*128 + 28*128) * 4 + 28*512*2)

__global__ void k5_attn1()
{
    extern __shared__ float sm5[];
    float* sq = sm5;                               // [10][128]
    float* sk = sm5 + 10*128;                      // [28][128]
    __half* sv = (__half*)(sm5 + 10*128 + 28*128); // [28][512]

    int w0 = blockIdx.x * 10, h = blockIdx.y, b = blockIdx.z;
    int tid = threadIdx.x, lane = tid & 31, wrp = tid >> 5;  // 16 warps
    __shared__ float ssc[10][10];
    __shared__ float cm4[10][40];

    const float* qkbase = d_qk1 + (size_t)b * 6 * 1504 * 256;
    const __half* vbase = d_v1 + (size_t)b * 6 * 1504 * 512;

    for (int idx = tid; idx < 320; idx += 512) {
        int p = idx >> 5, c4 = idx & 31;
        ((float4*)sq)[p*32 + c4] =
            *(const float4*)(qkbase + ((h+1)*1504 + (w0+2+p))*256 + c4*4);
    }
    for (int idx = tid; idx < 896; idx += 512) {
        int r = idx >> 5, c4 = idx & 31;
        int i = r / 14, jj = r % 14;
        ((float4*)(sk + r*128))[c4] =
            *(const float4*)(qkbase + ((h+i)*1504 + (w0+jj))*256 + 128 + c4*4);
    }
    for (int idx = tid; idx < 1792; idx += 512) {
        int r = idx >> 6, c4 = idx & 63;
        int i = r / 14, jj = r % 14;
        ((uint4*)(sv + r*512))[c4] =
            *(const uint4*)(vbase + ((h+i)*1504 + (w0+jj))*512 + c4*8);
    }
    __syncthreads();

    for (int pair = wrp; pair < 100; pair += 16) {
        int p = pair / 10, kl = pair % 10;
        int i = kl / 5, j = kl % 5;
        float4 q4 = ((const float4*)(sq + p*128))[lane];
        float4 k4 = ((const float4*)(sk + (i*14 + p + j)*128))[lane];
        float s = q4.x*k4.x + q4.y*k4.y + q4.z*k4.z + q4.w*k4.w;
        #pragma unroll
        for (int off = 16; off; off >>= 1) s += __shfl_xor_sync(0xffffffffu, s, off);
        if (lane == 0) ssc[p][kl] = s;
    }
    __syncthreads();
    if (tid < 10) {
        float mx = -1e30f;
        #pragma unroll
        for (int kl = 0; kl < 10; kl++) mx = fmaxf(mx, ssc[tid][kl]);
        float e[10], s = 0.f;
        #pragma unroll
        for (int kl = 0; kl < 10; kl++) { e[kl] = __expf(ssc[tid][kl]-mx); s += e[kl]; }
        float inv = 1.f / s;
        #pragma unroll
        for (int kl = 0; kl < 10; kl++) {
            float a = e[kl] * inv;
            #pragma unroll
            for (int m = 0; m < 4; m++) cm4[tid][kl*4+m] = a * d_emb1[m*10+kl];
        }
    }
    __syncthreads();

    int o = tid & 127;
    int ph = tid >> 7;
    float s1 = 0.f, s2 = 0.f;
    for (int p = ph; p < 10; p += 4) {
        const float* cw = cm4[p];
        float acc = 0.f;
        #pragma unroll
        for (int kl = 0; kl < 10; kl++) {
            int i = kl / 5, j = kl % 5;
            uint2 pv = *(const uint2*)(sv + (i*14 + p + j)*512 + o*4);
            float2 v01 = __half22float2(*(const __half2*)&pv.x);
            float2 v23 = __half22float2(*(const __half2*)&pv.y);
            acc += cw[kl*4]*v01.x + cw[kl*4+1]*v01.y + cw[kl*4+2]*v23.x + cw[kl*4+3]*v23.y;
        }
        s1 += acc; s2 += acc*acc;
        if (!(h & 1) && !((w0+p) & 1))
            d_o1raw[((b*2 + (h>>1))*750 + ((w0+p)>>1))*128 + o] = acc;
    }
    atomicAdd(&P_SUM1[o], s1);
    atomicAdd(&P_SUMSQ1[o], s2);
}

// ---------------------------------------------------------------------------
// K8: stage2 qkv GEMM, ILP-split dots, 8 positions/block.
// grid (95, 2, 2), block 256.
// ---------------------------------------------------------------------------
#define K8_SMEM ((128*96 + 8*128) * 4)

__global__ void k8_gemm2(const float* g1, const float* b1)
{
    extern __shared__ float sm8[];
    float* sWt = sm8;               // [128][96]
    float* sa  = sm8 + 128*96;      // [8][128]
    __shared__ float sScale[128], sShift[128];

    int t = threadIdx.x;
    int hp = blockIdx.y, b = blockIdx.z;
    int W0 = blockIdx.x * 8;

    if (t < 128) {
        float n = 12000.f;
        float mean = P_SUM1[t] / n;
        float var  = P_SUMSQ1[t] / n - mean*mean;
        float sc = g1[t] * rsqrtf(var + 1e-5f);
        sScale[t] = sc;
        sShift[t] = b1[t] - mean*sc;
    }
    for (int idx = t; idx < 3072; idx += 256)
        ((float4*)sWt)[idx] = ((const float4*)d_Wcat2)[idx];
    __syncthreads();

    for (int idx = t; idx < 1024; idx += 256) {
        int ps = idx >> 7, i = idx & 127;
        int wp = W0 + ps;
        float v = 0.f;
        if (wp >= 2 && wp < 752) {
            float raw = d_o1raw[(((b*2 + hp)*750) + (wp-2))*128 + i];
            v = fmaxf(fmaf(raw, sScale[i], sShift[i]), 0.f);
        }
        sa[ps*128 + i] = v;
    }
    __syncthreads();

    #pragma unroll
    for (int k = 0; k < 3; k++) {
        int pair = t + k*256;
        int ps = pair / 96, o = pair - (pair/96)*96;
        int wp = W0 + ps;
        if (wp >= 754) continue;
        const float* av = sa + ps*128;
        float a0 = 0.f, a1 = 0.f, a2 = 0.f, a3 = 0.f;
        #pragma unroll
        for (int c = 0; c < 32; c++) {
            a0 = fmaf(av[c],     sWt[c*96 + o],        a0);
            a1 = fmaf(av[c+32],  sWt[(c+32)*96 + o],   a1);
            a2 = fmaf(av[c+64],  sWt[(c+64)*96 + o],   a2);
            a3 = fmaf(av[c+96],  sWt[(c+96)*96 + o],   a3);
        }
        d_qkv2[(((b*2 + hp)*754) + wp)*96 + o] = (a0 + a1) + (a2 + a3);
    }
}

// ---------------------------------------------------------------------------
// K9: stage2 attention combine, warp per position. grid (188, 2), block 128
// ---------------------------------------------------------------------------
__global__ void k9_attn2()
{
    __shared__ float semb[40];
    int tid = threadIdx.x;
    if (tid < 40) { int kl = tid >> 2, m = tid & 3; semb[tid] = d_emb2[m*10+kl]; }
    __syncthreads();

    int lane = tid & 31, wrp = tid >> 5;
    int w = blockIdx.x * 4 + wrp, b = blockIdx.y;
    if (w >= 750) return;

    const float* base = d_qkv2 + (size_t)b * 2 * 754 * 96;
    const float* qp = base + (w + 2) * 96;
    float qv = (lane < 16) ? qp[lane] : 0.f;

    float scl[10];
    float mx = -1e30f;
    #pragma unroll
    for (int kl = 0; kl < 10; kl++) {
        int i = kl / 5, j = kl % 5;
        const float* kp = base + (i*754 + (w+j))*96 + 16;
        float pr = (lane < 16) ? qv * kp[lane] : 0.f;
        #pragma unroll
        for (int off = 8; off; off >>= 1) pr += __shfl_xor_sync(0xffffffffu, pr, off);
        scl[kl] = pr;
        mx = fmaxf(mx, pr);
    }
    float s = 0.f;
    #pragma unroll
    for (int kl = 0; kl < 10; kl++) { scl[kl] = __expf(scl[kl]-mx); s += scl[kl]; }
    float inv = 1.f / s;
    if (lane < 16) {
        float acc = 0.f;
        #pragma unroll
        for (int kl = 0; kl < 10; kl++) {
            int i = kl / 5, j = kl % 5;
            float4 v = *(const float4*)(base + (i*754 + (w+j))*96 + 32 + lane*4);
            float aw = scl[kl] * inv;
            acc += aw * (semb[kl*4]*v.x + semb[kl*4+1]*v.y + semb[kl*4+2]*v.z + semb[kl*4+3]*v.w);
        }
        d_out2[(b*750 + w)*16 + lane] = acc;
        atomicAdd(&P_SUM2[lane], acc);
        atomicAdd(&P_SUMSQ2[lane], acc*acc);
    }
}

// ---------------------------------------------------------------------------
// K11: stage2 BN + ReLU + AvgPool(1,56) -> out. grid (13,16,2), block 64
// ---------------------------------------------------------------------------
__global__ void k11_final(float* out, const float* g2, const float* b2)
{
    int n = blockIdx.x, c = blockIdx.y, b = blockIdx.z;
    int t = threadIdx.x;
    float nn = 1500.f;
    float mean = P_SUM2[c] / nn;
    float var  = P_SUMSQ2[c] / nn - mean*mean;
    float sc = g2[c] * rsqrtf(var + 1e-5f);
    float sf = b2[c] - mean * sc;

    float v = 0.f;
    if (t < 56) {
        float raw = d_out2[(b*750 + n*56 + t)*16 + c];
        v = fmaxf(fmaf(raw, sc, sf), 0.f);
    }
    __shared__ float shm[64];
    shm[t] = v;
    __syncthreads();
    for (int st = 32; st; st >>= 1) {
        if (t < st) shm[t] += shm[t+st];
        __syncthreads();
    }
    if (t == 0) out[(b*16 + c)*13 + n] = shm[0] * (1.f/56.f);
}

// ---------------------------------------------------------------------------
extern "C" void kernel_launch(void* const* d_in, const int* in_sizes, int n_in,
                              void* d_out, int out_size)
{
    const float* x     = (const float*)d_in[0];
    const float* p0_q  = (const float*)d_in[1];
    const float* p0_k  = (const float*)d_in[2];
    const float* p0_v  = (const float*)d_in[3];
    const float* p0_ea = (const float*)d_in[4];
    const float* p0_eb = (const float*)d_in[5];
    const float* p0_em = (const float*)d_in[6];
    const float* p0_g  = (const float*)d_in[7];
    const float* p0_b  = (const float*)d_in[8];
    const float* p1_q  = (const float*)d_in[9];
    const float* p1_k  = (const float*)d_in[10];
    const float* p1_v  = (const float*)d_in[11];
    const float* p1_ea = (const float*)d_in[12];
    const float* p1_eb = (const float*)d_in[13];
    const float* p1_em = (const float*)d_in[14];
    const float* p1_g  = (const float*)d_in[15];
    const float* p1_b  = (const float*)d_in[16];
    const float* p2_q  = (const float*)d_in[17];
    const float* p2_k  = (const float*)d_in[18];
    const float* p2_v  = (const float*)d_in[19];
    const float* p2_ea = (const float*)d_in[20];
    const float* p2_eb = (const float*)d_in[21];
    const float* p2_em = (const float*)d_in[22];
    const float* p2_g  = (const float*)d_in[23];
    const float* p2_b  = (const float*)d_in[24];
    float* out = (float*)d_out;

    static int smem_set = 0;
    if (!smem_set) {
        cudaFuncSetAttribute(k4_gemm1, cudaFuncAttributeMaxDynamicSharedMemorySize, K4_SMEM);
        cudaFuncSetAttribute(k4_gemm1, cudaFuncAttributePreferredSharedMemoryCarveout,
                             cudaSharedmemCarveoutMaxShared);
        cudaFuncSetAttribute(k5_attn1, cudaFuncAttributeMaxDynamicSharedMemorySize, K5_SMEM);
        cudaFuncSetAttribute(k5_attn1, cudaFuncAttributePreferredSharedMemoryCarveout,
                             cudaSharedmemCarveoutMaxShared);
        cudaFuncSetAttribute(k8_gemm2, cudaFuncAttributeMaxDynamicSharedMemorySize, K8_SMEM);
        smem_set = 1;
    }

    k0_pre<<<17, 256>>>(p0_q, p0_k, p0_v, p0_ea, p0_eb, p0_em,
                        p1_q, p1_k, p1_v, p1_ea, p1_eb, p1_em,
                        p2_q, p2_k, p2_v, p2_ea, p2_eb, p2_em);
    k1_stem0<<<dim3(24, 8, 2), 128>>>(x);
    k3_h1<<<3000, 256>>>(p0_g, p0_b);
    k4_gemm1<<<dim3(94, 6), 256, K4_SMEM>>>();
    k5_attn1<<<dim3(150, 4, 2), 512, K5_SMEM>>>();
    k8_gemm2<<<dim3(95, 2, 2), 256, K8_SMEM>>>(p1_g, p1_b);
    k9_attn2<<<dim3(188, 2), 128>>>();
    k11_final<<<dim3(13, 16, 2), 64>>>(out, p2_g, p2_b);
}

// round 14
// speedup vs baseline: 1.1298x; 1.0358x over previous
#include <cuda_runtime.h>
#include <cuda_bf16.h>
#include <cuda_fp16.h>
#include <math.h>
#include <stdint.h>

// ---------------------------------------------------------------------------
// Static device scratch
// ---------------------------------------------------------------------------
__device__ float d_g0[5*12000];
__device__ __nv_bfloat16 d_h1h[12000*64];
__device__ __nv_bfloat16 d_h1l[12000*64];
__device__ __half d_h1f[12000*64];              // h1 in fp16 (for V blocks)
__device__ float d_qk1[2*6*1504*256];           // q cols 0..127, k cols 128..255 (fp32)
__device__ __half d_v1[2*6*1504*512];           // v cols (o*4+m) in fp16
__device__ float d_o1raw[2*2*750*128];
__device__ float d_qkv2[2*2*754*96];            // v cols = 32+o*4+m
__device__ float d_out2[2*750*16];

__device__ __nv_bfloat16 d_W1bh[768*64];        // [n][k] bf16 hi (q/k cols use this)
__device__ __nv_bfloat16 d_W1bl[768*64];        // lo
__device__ __half d_W1f[512*64];                // V cols only, fp16, [n-256][k]
__device__ float d_Wcat2[128*96];
__device__ float d_Weff0[5*64];
__device__ float d_emb1[4*10];
__device__ float d_emb2[4*10];
__device__ float d_C0;

// contiguous stats block, zeroed by k0 block 16:
// [0,30)=S0, [30,158)=sum1, [158,286)=sumsq1, [286,302)=sum2, [302,318)=sumsq2
__device__ float d_stats[318];
#define P_S0     (d_stats)
#define P_SUM1   (d_stats + 30)
#define P_SUMSQ1 (d_stats + 158)
#define P_SUM2   (d_stats + 286)
#define P_SUMSQ2 (d_stats + 302)

__device__ __forceinline__ void mma_bf16(float4& c,
    uint32_t a0, uint32_t a1, uint32_t a2, uint32_t a3,
    uint32_t b0, uint32_t b1)
{
    asm volatile(
        "mma.sync.aligned.m16n8k16.row.col.f32.bf16.bf16.f32 "
        "{%0,%1,%2,%3},{%4,%5,%6,%7},{%8,%9},{%0,%1,%2,%3};"
        : "+f"(c.x), "+f"(c.y), "+f"(c.z), "+f"(c.w)
        : "r"(a0), "r"(a1), "r"(a2), "r"(a3), "r"(b0), "r"(b1));
}

__device__ __forceinline__ void mma_fp16(float4& c,
    uint32_t a0, uint32_t a1, uint32_t a2, uint32_t a3,
    uint32_t b0, uint32_t b1)
{
    asm volatile(
        "mma.sync.aligned.m16n8k16.row.col.f32.f16.f16.f32 "
        "{%0,%1,%2,%3},{%4,%5,%6,%7},{%8,%9},{%0,%1,%2,%3};"
        : "+f"(c.x), "+f"(c.y), "+f"(c.z), "+f"(c.w)
        : "r"(a0), "r"(a1), "r"(a2), "r"(a3), "r"(b0), "r"(b1));
}

__device__ __forceinline__ void ldsm_x4(uint32_t& r0, uint32_t& r1, uint32_t& r2, uint32_t& r3,
                                        uint32_t addr)
{
    asm volatile("ldmatrix.sync.aligned.m8n8.x4.shared.b16 {%0,%1,%2,%3}, [%4];"
        : "=r"(r0), "=r"(r1), "=r"(r2), "=r"(r3) : "r"(addr));
}

// ---------------------------------------------------------------------------
// K0: grid 17 blocks. Blocks 0..15: weight conversion (bf16 hi/lo + fp16
//     plane for V cols + stage2 fp32). Block 16: embeddings, Weff0, C0, stats.
// ---------------------------------------------------------------------------
__global__ void k0_pre(const float* p0_q, const float* p0_k, const float* p0_v,
                       const float* p0_ea, const float* p0_eb, const float* p0_em,
                       const float* p1_q, const float* p1_k, const float* p1_v,
                       const float* p1_ea, const float* p1_eb, const float* p1_em,
                       const float* p2_q, const float* p2_k, const float* p2_v,
                       const float* p2_ea, const float* p2_eb, const float* p2_em)
{
    int t = threadIdx.x;
    int blk = blockIdx.x;

    if (blk < 16) {
        #pragma unroll
        for (int u = 0; u < 12; u++) {
            int idx = blk*3072 + u*256 + t;
            int j = idx / 64, c = idx % 64;
            float v;
            if (j < 128)       v = p1_q[c*128 + j];
            else if (j < 256)  v = p1_k[c*128 + (j-128)];
            else { int o = (j-256) >> 2, m = (j-256) & 3; v = p1_v[(m*64+c)*128 + o]; }
            __nv_bfloat16 hi = __float2bfloat16_rn(v);
            d_W1bh[idx] = hi;
            d_W1bl[idx] = __float2bfloat16_rn(v - __bfloat162float(hi));
            if (j >= 256) d_W1f[(j-256)*64 + c] = __float2half_rn(v);
        }
        #pragma unroll
        for (int u = 0; u < 3; u++) {
            int idx = blk*768 + u*256 + t;
            int c = idx / 96, j = idx % 96;
            float v;
            if (j < 16)       v = p2_q[c*16 + j];
            else if (j < 32)  v = p2_k[c*16 + (j-16)];
            else { int o = (j-32) >> 2, m = (j-32) & 3; v = p2_v[(m*128+c)*16 + o]; }
            d_Wcat2[idx] = v;
        }
        return;
    }

    // blk == 16: zero stats + small precomputes
    for (int i = t; i < 318; i += 256) d_stats[i] = 0.f;

    __shared__ float logit0[4][5], logit1[4][10], logit2[4][10];
    __shared__ float emb0s[4][5];

    if (t == 0) {
        float s = 0.f;
        for (int o = 0; o < 64; o++) s += p0_q[o] * p0_k[o];
        d_C0 = s;
    }
    if (t >= 128 && t < 148) {
        int u = t - 128; int m = u / 5, j = u % 5;
        float la = 0.f, lb = 0.f;
        for (int o = 0; o < 64; o++) {
            la += p0_em[m*64+o] * p0_ea[o];
            lb += p0_em[m*64+o] * p0_eb[o*5+j];
        }
        logit0[m][j] = la + lb;
    }
    if (t < 40) {
        int m = t / 10, kl = t % 10, i = kl / 5, j = kl % 5;
        float la = 0.f, lb = 0.f;
        for (int o = 0; o < 128; o++) {
            la += p1_em[m*128+o] * p1_ea[o*2+i];
            lb += p1_em[m*128+o] * p1_eb[o*5+j];
        }
        logit1[m][kl] = la + lb;
    }
    if (t >= 64 && t < 104) {
        int u = t - 64; int m = u / 10, kl = u % 10, i = kl / 5, j = kl % 5;
        float la = 0.f, lb = 0.f;
        for (int o = 0; o < 16; o++) {
            la += p2_em[m*16+o] * p2_ea[o*2+i];
            lb += p2_em[m*16+o] * p2_eb[o*5+j];
        }
        logit2[m][kl] = la + lb;
    }
    __syncthreads();
    if (t < 5) {
        float mx = -1e30f;
        for (int m = 0; m < 4; m++) mx = fmaxf(mx, logit0[m][t]);
        float e[4], s = 0.f;
        for (int m = 0; m < 4; m++) { e[m] = __expf(logit0[m][t]-mx); s += e[m]; }
        for (int m = 0; m < 4; m++) emb0s[m][t] = e[m] / s;
    }
    if (t >= 32 && t < 42) {
        int kl = t - 32;
        float mx = -1e30f;
        for (int m = 0; m < 4; m++) mx = fmaxf(mx, logit1[m][kl]);
        float e[4], s = 0.f;
        for (int m = 0; m < 4; m++) { e[m] = __expf(logit1[m][kl]-mx); s += e[m]; }
        for (int m = 0; m < 4; m++) d_emb1[m*10+kl] = e[m] / s;
    }
    if (t >= 64 && t < 74) {
        int kl = t - 64;
        float mx = -1e30f;
        for (int m = 0; m < 4; m++) mx = fmaxf(mx, logit2[m][kl]);
        float e[4], s = 0.f;
        for (int m = 0; m < 4; m++) { e[m] = __expf(logit2[m][kl]-mx); s += e[m]; }
        for (int m = 0; m < 4; m++) d_emb2[m*10+kl] = e[m] / s;
    }
    __syncthreads();
    for (int idx = t; idx < 5*64; idx += blockDim.x) {
        int l = idx / 64, o = idx % 64;
        float s = 0.f;
        for (int m = 0; m < 4; m++) s += emb0s[m][l] * p0_v[m*64+o];
        d_Weff0[idx] = s;
    }
}

// ---------------------------------------------------------------------------
// K1: stage0 attention -> g[5] + low-rank BN stats; also zero-fills the
// hp=0 pad rows of d_qk1/d_v1. grid (24,8,2), block 128
// ---------------------------------------------------------------------------
__global__ void k1_stem0(const float* x)
{
    int tid = threadIdx.x;
    int w = blockIdx.x * 128 + tid;
    int h = blockIdx.y, b = blockIdx.z;
    bool valid = (w < 3000);

    // pad zero-fill: 192512 float4 (qk) + 192512 uint4 (v) over 384 blocks
    {
        int blockId = (blockIdx.z * 8 + blockIdx.y) * 24 + blockIdx.x;
        #pragma unroll
        for (int u = 0; u < 4; u++) {
            int idx = (blockId * 4 + u) * 128 + tid;
            if (idx < 192512) {
                int fidx = idx * 4;
                int row = fidx >> 8, col = fidx & 255;
                int bb = row >= 1504; int wp = row - bb*1504;
                *(float4*)&d_qk1[((size_t)(bb*9024 + wp))*256 + col] =
                    make_float4(0.f,0.f,0.f,0.f);
                int eidx = idx * 8;
                int vrow = eidx >> 9, vcol = eidx & 511;
                int b2 = vrow >= 1504; int wp2 = vrow - b2*1504;
                *(uint4*)&d_v1[((size_t)(b2*9024 + wp2))*512 + vcol] =
                    make_uint4(0,0,0,0);
            }
        }
    }

    float g[5] = {0.f,0.f,0.f,0.f,0.f};
    if (valid) {
        const float* xr = x + (b*8 + h) * 3000;
        float xc = xr[w];
        float C0 = d_C0;
        float xl[5], sc[5];
        float mx = -1e30f;
        #pragma unroll
        for (int l = 0; l < 5; l++) {
            int c = w + l - 2;
            xl[l] = (c >= 0 && c < 3000) ? xr[c] : 0.f;
            sc[l] = xc * xl[l] * C0;
            mx = fmaxf(mx, sc[l]);
        }
        float s = 0.f;
        #pragma unroll
        for (int l = 0; l < 5; l++) { sc[l] = __expf(sc[l]-mx); s += sc[l]; }
        float inv = 1.f / s;
        #pragma unroll
        for (int l = 0; l < 5; l++) g[l] = sc[l] * inv * xl[l];
    }

    float st[20];
    {
        int si = 0;
        #pragma unroll
        for (int l = 0; l < 5; l++) st[si++] = g[l];
        #pragma unroll
        for (int l = 0; l < 5; l++)
            #pragma unroll
            for (int l2 = l; l2 < 5; l2++) st[si++] = g[l]*g[l2];
    }
    #pragma unroll
    for (int i = 0; i < 20; i++)
        #pragma unroll
        for (int off = 16; off; off >>= 1)
            st[i] += __shfl_xor_sync(0xffffffffu, st[i], off);

    __shared__ float red[4][20];
    int lane = tid & 31, wrp = tid >> 5;
    if (lane == 0)
        for (int i = 0; i < 20; i++) red[wrp][i] = st[i];
    __syncthreads();
    if (tid < 20) {
        float v = red[0][tid] + red[1][tid] + red[2][tid] + red[3][tid];
        int slot;
        if (tid < 5) slot = tid;
        else {
            int k = tid - 5, l = 0;
            while (k >= 5 - l) { k -= 5 - l; l++; }
            slot = 5 + l*5 + (l + k);
        }
        atomicAdd(&P_S0[slot], v);
    }

    if (valid && !(h & 1) && !(w & 1)) {
        int p = b*6000 + (h>>1)*1500 + (w>>1);
        #pragma unroll
        for (int l = 0; l < 5; l++) d_g0[l*12000 + p] = g[l];
    }
}

// ---------------------------------------------------------------------------
// K3: stage0 BN + ReLU -> h1 bf16 hi/lo + fp16. grid 3000, block 256
// ---------------------------------------------------------------------------
__global__ void k3_h1(const float* g0, const float* b0)
{
    __shared__ float sW[5*64];
    __shared__ float sScale[64], sShift[64];
    int tid = threadIdx.x;
    for (int i = tid; i < 320; i += 256) sW[i] = d_Weff0[i];
    __syncthreads();
    if (tid < 64) {
        int c = tid;
        float Wc[5];
        #pragma unroll
        for (int l = 0; l < 5; l++) Wc[l] = sW[l*64 + c];
        float mn = 0.f, mq = 0.f;
        #pragma unroll
        for (int l = 0; l < 5; l++) {
            mn += P_S0[l] * Wc[l];
            #pragma unroll
            for (int l2 = 0; l2 < 5; l2++) {
                int lo = l < l2 ? l : l2, hi = l < l2 ? l2 : l;
                mq += P_S0[5 + lo*5 + hi] * Wc[l] * Wc[l2];
            }
        }
        float n = 48000.f;
        float mean = mn / n;
        float var  = mq / n - mean*mean;
        float sc = g0[c] * rsqrtf(var + 1e-5f);
        sScale[c] = sc;
        sShift[c] = b0[c] - mean * sc;
    }
    __syncthreads();

    int c = tid & 63;
    int p = blockIdx.x * 4 + (tid >> 6);
    float a = 0.f;
    #pragma unroll
    for (int l = 0; l < 5; l++) a += d_g0[l*12000 + p] * sW[l*64 + c];
    float y = fmaxf(fmaf(a, sScale[c], sShift[c]), 0.f);
    __nv_bfloat16 hi = __float2bfloat16_rn(y);
    d_h1h[p*64 + c] = hi;
    d_h1l[p*64 + c] = __float2bfloat16_rn(y - __bfloat162float(hi));
    d_h1f[p*64 + c] = __float2half_rn(y);
}

// ---------------------------------------------------------------------------
// K4: stage1 qkv GEMM (real rows, M'=12032). grid (94, 6), block 256.
// y=0,1: q/k cols, 3-term bf16 hi/lo (fp32 out).
// y=2..5: V cols, single-term fp16 (fp16 out).
// BM=128, BN=128, 4x2 warp layout (Mw=32, Nw=64).
// ---------------------------------------------------------------------------
#define K4_SMEM ((128*72 + 128*72 + 128*72 + 128*72) * 2)

__global__ void __launch_bounds__(256) k4_gemm1()
{
    extern __shared__ __nv_bfloat16 sh[];
    int tid = threadIdx.x;
    int rowBase = blockIdx.x * 128;
    int colBase = blockIdx.y * 128;
    bool isQK = (colBase < 256);

    int lane = tid & 31, wid = tid >> 5;
    int g = lane >> 2, tg = lane & 3;
    int mr   = (wid >> 1) * 32;
    int ncol = (wid & 1) * 64;

    int arow = (lane < 16) ? lane : (lane - 16);
    int acol = (lane < 16) ? 0 : 8;
    int brow = (lane & 7) + ((lane >> 4) << 3);
    int bcol = ((lane >> 3) & 1) * 8;

    if (isQK) {
        __nv_bfloat16* Ah = sh;               // [128][72]
        __nv_bfloat16* Al = Ah + 128*72;
        __nv_bfloat16* Bh = Al + 128*72;      // [128 n][72 k]
        __nv_bfloat16* Bl = Bh + 128*72;

        // A tile staging (hi/lo)
        {
            int r = tid >> 1;
            int half = (tid & 1) * 32;
            int prow = rowBase + r;
            int b = prow / 6016; int rem = prow % 6016;
            int hp = 1 + rem / 1504; int wp = rem % 1504;
            bool valid = (wp >= 2 && wp < 1502);
            __nv_bfloat16* dh = Ah + r*72 + half;
            __nv_bfloat16* dl = Al + r*72 + half;
            if (valid) {
                int pos = ((b*4 + (hp-1))*1500 + (wp-2))*64 + half;
                const uint4* sH = (const uint4*)(d_h1h + pos);
                const uint4* sL = (const uint4*)(d_h1l + pos);
                #pragma unroll
                for (int u = 0; u < 4; u++) {
                    ((uint4*)dh)[u] = sH[u];
                    ((uint4*)dl)[u] = sL[u];
                }
            } else {
                uint4 z = make_uint4(0,0,0,0);
                #pragma unroll
                for (int u = 0; u < 4; u++) { ((uint4*)dh)[u] = z; ((uint4*)dl)[u] = z; }
            }
        }
        // B tile staging
        {
            int n = tid >> 1;
            int seg = (tid & 1) * 32;
            const uint4* sH = (const uint4*)(d_W1bh + (colBase + n)*64 + seg);
            const uint4* sL = (const uint4*)(d_W1bl + (colBase + n)*64 + seg);
            uint4* dh = (uint4*)(Bh + n*72 + seg);
            uint4* dl = (uint4*)(Bl + n*72 + seg);
            #pragma unroll
            for (int u = 0; u < 4; u++) { dh[u] = sH[u]; dl[u] = sL[u]; }
        }
        __syncthreads();

        uint32_t aAddrH[2], aAddrL[2];
        #pragma unroll
        for (int mt = 0; mt < 2; mt++) {
            aAddrH[mt] = (uint32_t)__cvta_generic_to_shared(Ah + (mr + mt*16 + arow)*72 + acol);
            aAddrL[mt] = (uint32_t)__cvta_generic_to_shared(Al + (mr + mt*16 + arow)*72 + acol);
        }
        uint32_t bAddrH[4], bAddrL[4];
        #pragma unroll
        for (int pr = 0; pr < 4; pr++) {
            bAddrH[pr] = (uint32_t)__cvta_generic_to_shared(Bh + (ncol + pr*16 + brow)*72 + bcol);
            bAddrL[pr] = (uint32_t)__cvta_generic_to_shared(Bl + (ncol + pr*16 + brow)*72 + bcol);
        }

        float4 acc[2][8];
        #pragma unroll
        for (int i = 0; i < 2; i++)
            #pragma unroll
            for (int j = 0; j < 8; j++) acc[i][j] = make_float4(0.f,0.f,0.f,0.f);

        #pragma unroll
        for (int ks = 0; ks < 4; ks++) {
            uint32_t koff = ks * 32;
            uint32_t ah[2][4], al[2][4];
            #pragma unroll
            for (int mt = 0; mt < 2; mt++) {
                ldsm_x4(ah[mt][0],ah[mt][1],ah[mt][2],ah[mt][3], aAddrH[mt] + koff);
                ldsm_x4(al[mt][0],al[mt][1],al[mt][2],al[mt][3], aAddrL[mt] + koff);
            }
            #pragma unroll
            for (int pr = 0; pr < 4; pr++) {
                uint32_t bh0,bh1,bh2,bh3, bl0,bl1,bl2,bl3;
                ldsm_x4(bh0,bh1,bh2,bh3, bAddrH[pr] + koff);
                ldsm_x4(bl0,bl1,bl2,bl3, bAddrL[pr] + koff);
                #pragma unroll
                for (int mt = 0; mt < 2; mt++) {
                    mma_bf16(acc[mt][2*pr  ], ah[mt][0],ah[mt][1],ah[mt][2],ah[mt][3], bh0,bh1);
                    mma_bf16(acc[mt][2*pr  ], ah[mt][0],ah[mt][1],ah[mt][2],ah[mt][3], bl0,bl1);
                    mma_bf16(acc[mt][2*pr  ], al[mt][0],al[mt][1],al[mt][2],al[mt][3], bh0,bh1);
                    mma_bf16(acc[mt][2*pr+1], ah[mt][0],ah[mt][1],ah[mt][2],ah[mt][3], bh2,bh3);
                    mma_bf16(acc[mt][2*pr+1], ah[mt][0],ah[mt][1],ah[mt][2],ah[mt][3], bl2,bl3);
                    mma_bf16(acc[mt][2*pr+1], al[mt][0],al[mt][1],al[mt][2],al[mt][3], bh2,bh3);
                }
            }
        }

        #pragma unroll
        for (int mt = 0; mt < 2; mt++) {
            #pragma unroll
            for (int half = 0; half < 2; half++) {
                int prow = rowBase + mr + mt*16 + half*8 + g;
                int b = prow / 6016; int rem = prow % 6016;
                int hp = 1 + rem / 1504; int wp = rem % 1504;
                size_t orow = (size_t)(b*6 + hp)*1504 + wp;
                #pragma unroll
                for (int j = 0; j < 8; j++) {
                    int col = colBase + ncol + j*8 + tg*2;
                    float2 v = half ? make_float2(acc[mt][j].z, acc[mt][j].w)
                                    : make_float2(acc[mt][j].x, acc[mt][j].y);
                    *(float2*)&d_qk1[orow*256 + col] = v;
                }
            }
        }
    } else {
        // V path: single-term fp16
        __half* Af = (__half*)sh;             // [128][72]
        __half* Bf = Af + 128*72;             // [128 n][72 k]
        int vcolBase = colBase - 256;         // 0..383

        // A tile staging (fp16 single)
        {
            int r = tid >> 1;
            int half = (tid & 1) * 32;
            int prow = rowBase + r;
            int b = prow / 6016; int rem = prow % 6016;
            int hp = 1 + rem / 1504; int wp = rem % 1504;
            bool valid = (wp >= 2 && wp < 1502);
            __half* df = Af + r*72 + half;
            if (valid) {
                int pos = ((b*4 + (hp-1))*1500 + (wp-2))*64 + half;
                const uint4* sF = (const uint4*)(d_h1f + pos);
                #pragma unroll
                for (int u = 0; u < 4; u++) ((uint4*)df)[u] = sF[u];
            } else {
                uint4 z = make_uint4(0,0,0,0);
                #pragma unroll
                for (int u = 0; u < 4; u++) ((uint4*)df)[u] = z;
            }
        }
        // B tile staging (fp16)
        {
            int n = tid >> 1;
            int seg = (tid & 1) * 32;
            const uint4* sF = (const uint4*)(d_W1f + (vcolBase + n)*64 + seg);
            uint4* df = (uint4*)(Bf + n*72 + seg);
            #pragma unroll
            for (int u = 0; u < 4; u++) df[u] = sF[u];
        }
        __syncthreads();

        uint32_t aAddr[2];
        #pragma unroll
        for (int mt = 0; mt < 2; mt++)
            aAddr[mt] = (uint32_t)__cvta_generic_to_shared(Af + (mr + mt*16 + arow)*72 + acol);
        uint32_t bAddr[4];
        #pragma unroll
        for (int pr = 0; pr < 4; pr++)
            bAddr[pr] = (uint32_t)__cvta_generic_to_shared(Bf + (ncol + pr*16 + brow)*72 + bcol);

        float4 acc[2][8];
        #pragma unroll
        for (int i = 0; i < 2; i++)
            #pragma unroll
            for (int j = 0; j < 8; j++) acc[i][j] = make_float4(0.f,0.f,0.f,0.f);

        #pragma unroll
        for (int ks = 0; ks < 4; ks++) {
            uint32_t koff = ks * 32;
            uint32_t af[2][4];
            #pragma unroll
            for (int mt = 0; mt < 2; mt++)
                ldsm_x4(af[mt][0],af[mt][1],af[mt][2],af[mt][3], aAddr[mt] + koff);
            #pragma unroll
            for (int pr = 0; pr < 4; pr++) {
                uint32_t b0,b1,b2,b3;
                ldsm_x4(b0,b1,b2,b3, bAddr[pr] + koff);
                #pragma unroll
                for (int mt = 0; mt < 2; mt++) {
                    mma_fp16(acc[mt][2*pr  ], af[mt][0],af[mt][1],af[mt][2],af[mt][3], b0,b1);
                    mma_fp16(acc[mt][2*pr+1], af[mt][0],af[mt][1],af[mt][2],af[mt][3], b2,b3);
                }
            }
        }

        #pragma unroll
        for (int mt = 0; mt < 2; mt++) {
            #pragma unroll
            for (int half = 0; half < 2; half++) {
                int prow = rowBase + mr + mt*16 + half*8 + g;
                int b = prow / 6016; int rem = prow % 6016;
                int hp = 1 + rem / 1504; int wp = rem % 1504;
                size_t orow = (size_t)(b*6 + hp)*1504 + wp;
                #pragma unroll
                for (int j = 0; j < 8; j++) {
                    int col = vcolBase + ncol + j*8 + tg*2;
                    float2 v = half ? make_float2(acc[mt][j].z, acc[mt][j].w)
                                    : make_float2(acc[mt][j].x, acc[mt][j].y);
                    __half2 hv;
                    hv.x = __float2half_rn(v.x);
                    hv.y = __float2half_rn(v.y);
                    *(__half2*)&d_v1[orow*512 + col] = hv;
                }
            }
        }
    }
}

// ---------------------------------------------------------------------------
// K5: stage1 attention combine, smem-staged q(fp32)/k(fp32)/v(fp16) window.
// 10 positions/block, 512 threads. grid (150, 4, 2).
// ---------------------------------------------------------------------------
#define K5_SMEM ((10*128 + 28*128) * 4 + 28*512*2)

__global__ void k5_attn1()
{
    extern __shared__ float sm5[];
    float* sq = sm5;                               // [10][128]
    float* sk = sm5 + 10*128;                      // [28][128]
    __half* sv = (__half*)(sm5 + 10*128 + 28*128); // [28][512]

    int w0 = blockIdx.x * 10, h = blockIdx.y, b = blockIdx.z;
    int tid = threadIdx.x, lane = tid & 31, wrp = tid >> 5;  // 16 warps
    __shared__ float ssc[10][10];
    __shared__ float cm4[10][40];

    const float* qkbase = d_qk1 + (size_t)b * 6 * 1504 * 256;
    const __half* vbase = d_v1 + (size_t)b * 6 * 1504 * 512;

    for (int idx = tid; idx < 320; idx += 512) {
        int p = idx >> 5, c4 = idx & 31;
        ((float4*)sq)[p*32 + c4] =
            *(const float4*)(qkbase + ((h+1)*1504 + (w0+2+p))*256 + c4*4);
    }
    for (int idx = tid; idx < 896; idx += 512) {
        int r = idx >> 5, c4 = idx & 31;
        int i = r / 14, jj = r % 14;
        ((float4*)(sk + r*128))[c4] =
            *(const float4*)(qkbase + ((h+i)*1504 + (w0+jj))*256 + 128 + c4*4);
    }
    for (int idx = tid; idx < 1792; idx += 512) {
        int r = idx >> 6, c4 = idx & 63;
        int i = r / 14, jj = r % 14;
        ((uint4*)(sv + r*512))[c4] =
            *(const uint4*)(vbase + ((h+i)*1504 + (w0+jj))*512 + c4*8);
    }
    __syncthreads();

    for (int pair = wrp; pair < 100; pair += 16) {
        int p = pair / 10, kl = pair % 10;
        int i = kl / 5, j = kl % 5;
        float4 q4 = ((const float4*)(sq + p*128))[lane];
        float4 k4 = ((const float4*)(sk + (i*14 + p + j)*128))[lane];
        float s = q4.x*k4.x + q4.y*k4.y + q4.z*k4.z + q4.w*k4.w;
        #pragma unroll
        for (int off = 16; off; off >>= 1) s += __shfl_xor_sync(0xffffffffu, s, off);
        if (lane == 0) ssc[p][kl] = s;
    }
    __syncthreads();
    if (tid < 10) {
        float mx = -1e30f;
        #pragma unroll
        for (int kl = 0; kl < 10; kl++) mx = fmaxf(mx, ssc[tid][kl]);
        float e[10], s = 0.f;
        #pragma unroll
        for (int kl = 0; kl < 10; kl++) { e[kl] = __expf(ssc[tid][kl]-mx); s += e[kl]; }
        float inv = 1.f / s;
        #pragma unroll
        for (int kl = 0; kl < 10; kl++) {
            float a = e[kl] * inv;
            #pragma unroll
            for (int m = 0; m < 4; m++) cm4[tid][kl*4+m] = a * d_emb1[m*10+kl];
        }
    }
    __syncthreads();

    int o = tid & 127;
    int ph = tid >> 7;
    float s1 = 0.f, s2 = 0.f;
    for (int p = ph; p < 10; p += 4) {
        const float* cw = cm4[p];
        float acc = 0.f;
        #pragma unroll
        for (int kl = 0; kl < 10; kl++) {
            int i = kl / 5, j = kl % 5;
            uint2 pv = *(const uint2*)(sv + (i*14 + p + j)*512 + o*4);
            float2 v01 = __half22float2(*(const __half2*)&pv.x);
            float2 v23 = __half22float2(*(const __half2*)&pv.y);
            acc += cw[kl*4]*v01.x + cw[kl*4+1]*v01.y + cw[kl*4+2]*v23.x + cw[kl*4+3]*v23.y;
        }
        s1 += acc; s2 += acc*acc;
        if (!(h & 1) && !((w0+p) & 1))
            d_o1raw[((b*2 + (h>>1))*750 + ((w0+p)>>1))*128 + o] = acc;
    }
    atomicAdd(&P_SUM1[o], s1);
    atomicAdd(&P_SUMSQ1[o], s2);
}

// ---------------------------------------------------------------------------
// K8: stage2 qkv GEMM, ILP-split dots, 8 positions/block.
// grid (95, 2, 2), block 256.
// ---------------------------------------------------------------------------
#define K8_SMEM ((128*96 + 8*128) * 4)

__global__ void k8_gemm2(const float* g1, const float* b1)
{
    extern __shared__ float sm8[];
    float* sWt = sm8;               // [128][96]
    float* sa  = sm8 + 128*96;      // [8][128]
    __shared__ float sScale[128], sShift[128];

    int t = threadIdx.x;
    int hp = blockIdx.y, b = blockIdx.z;
    int W0 = blockIdx.x * 8;

    if (t < 128) {
        float n = 12000.f;
        float mean = P_SUM1[t] / n;
        float var  = P_SUMSQ1[t] / n - mean*mean;
        float sc = g1[t] * rsqrtf(var + 1e-5f);
        sScale[t] = sc;
        sShift[t] = b1[t] - mean*sc;
    }
    for (int idx = t; idx < 3072; idx += 256)
        ((float4*)sWt)[idx] = ((const float4*)d_Wcat2)[idx];
    __syncthreads();

    for (int idx = t; idx < 1024; idx += 256) {
        int ps = idx >> 7, i = idx & 127;
        int wp = W0 + ps;
        float v = 0.f;
        if (wp >= 2 && wp < 752) {
            float raw = d_o1raw[(((b*2 + hp)*750) + (wp-2))*128 + i];
            v = fmaxf(fmaf(raw, sScale[i], sShift[i]), 0.f);
        }
        sa[ps*128 + i] = v;
    }
    __syncthreads();

    #pragma unroll
    for (int k = 0; k < 3; k++) {
        int pair = t + k*256;
        int ps = pair / 96, o = pair - (pair/96)*96;
        int wp = W0 + ps;
        if (wp >= 754) continue;
        const float* av = sa + ps*128;
        float a0 = 0.f, a1 = 0.f, a2 = 0.f, a3 = 0.f;
        #pragma unroll
        for (int c = 0; c < 32; c++) {
            a0 = fmaf(av[c],     sWt[c*96 + o],        a0);
            a1 = fmaf(av[c+32],  sWt[(c+32)*96 + o],   a1);
            a2 = fmaf(av[c+64],  sWt[(c+64)*96 + o],   a2);
            a3 = fmaf(av[c+96],  sWt[(c+96)*96 + o],   a3);
        }
        d_qkv2[(((b*2 + hp)*754) + wp)*96 + o] = (a0 + a1) + (a2 + a3);
    }
}

// ---------------------------------------------------------------------------
// K9: stage2 attention combine, warp per position. grid (188, 2), block 128
// ---------------------------------------------------------------------------
__global__ void k9_attn2()
{
    __shared__ float semb[40];
    int tid = threadIdx.x;
    if (tid < 40) { int kl = tid >> 2, m = tid & 3; semb[tid] = d_emb2[m*10+kl]; }
    __syncthreads();

    int lane = tid & 31, wrp = tid >> 5;
    int w = blockIdx.x * 4 + wrp, b = blockIdx.y;
    if (w >= 750) return;

    const float* base = d_qkv2 + (size_t)b * 2 * 754 * 96;
    const float* qp = base + (w + 2) * 96;
    float qv = (lane < 16) ? qp[lane] : 0.f;

    float scl[10];
    float mx = -1e30f;
    #pragma unroll
    for (int kl = 0; kl < 10; kl++) {
        int i = kl / 5, j = kl % 5;
        const float* kp = base + (i*754 + (w+j))*96 + 16;
        float pr = (lane < 16) ? qv * kp[lane] : 0.f;
        #pragma unroll
        for (int off = 8; off; off >>= 1) pr += __shfl_xor_sync(0xffffffffu, pr, off);
        scl[kl] = pr;
        mx = fmaxf(mx, pr);
    }
    float s = 0.f;
    #pragma unroll
    for (int kl = 0; kl < 10; kl++) { scl[kl] = __expf(scl[kl]-mx); s += scl[kl]; }
    float inv = 1.f / s;
    if (lane < 16) {
        float acc = 0.f;
        #pragma unroll
        for (int kl = 0; kl < 10; kl++) {
            int i = kl / 5, j = kl % 5;
            float4 v = *(const float4*)(base + (i*754 + (w+j))*96 + 32 + lane*4);
            float aw = scl[kl] * inv;
            acc += aw * (semb[kl*4]*v.x + semb[kl*4+1]*v.y + semb[kl*4+2]*v.z + semb[kl*4+3]*v.w);
        }
        d_out2[(b*750 + w)*16 + lane] = acc;
        atomicAdd(&P_SUM2[lane], acc);
        atomicAdd(&P_SUMSQ2[lane], acc*acc);
    }
}

// ---------------------------------------------------------------------------
// K11: stage2 BN + ReLU + AvgPool(1,56) -> out. grid (13,16,2), block 64
// ---------------------------------------------------------------------------
__global__ void k11_final(float* out, const float* g2, const float* b2)
{
    int n = blockIdx.x, c = blockIdx.y, b = blockIdx.z;
    int t = threadIdx.x;
    float nn = 1500.f;
    float mean = P_SUM2[c] / nn;
    float var  = P_SUMSQ2[c] / nn - mean*mean;
    float sc = g2[c] * rsqrtf(var + 1e-5f);
    float sf = b2[c] - mean * sc;

    float v = 0.f;
    if (t < 56) {
        float raw = d_out2[(b*750 + n*56 + t)*16 + c];
        v = fmaxf(fmaf(raw, sc, sf), 0.f);
    }
    __shared__ float shm[64];
    shm[t] = v;
    __syncthreads();
    for (int st = 32; st; st >>= 1) {
        if (t < st) shm[t] += shm[t+st];
        __syncthreads();
    }
    if (t == 0) out[(b*16 + c)*13 + n] = shm[0] * (1.f/56.f);
}

// ---------------------------------------------------------------------------
extern "C" void kernel_launch(void* const* d_in, const int* in_sizes, int n_in,
                              void* d_out, int out_size)
{
    const float* x     = (const float*)d_in[0];
    const float* p0_q  = (const float*)d_in[1];
    const float* p0_k  = (const float*)d_in[2];
    const float* p0_v  = (const float*)d_in[3];
    const float* p0_ea = (const float*)d_in[4];
    const float* p0_eb = (const float*)d_in[5];
    const float* p0_em = (const float*)d_in[6];
    const float* p0_g  = (const float*)d_in[7];
    const float* p0_b  = (const float*)d_in[8];
    const float* p1_q  = (const float*)d_in[9];
    const float* p1_k  = (const float*)d_in[10];
    const float* p1_v  = (const float*)d_in[11];
    const float* p1_ea = (const float*)d_in[12];
    const float* p1_eb = (const float*)d_in[13];
    const float* p1_em = (const float*)d_in[14];
    const float* p1_g  = (const float*)d_in[15];
    const float* p1_b  = (const float*)d_in[16];
    const float* p2_q  = (const float*)d_in[17];
    const float* p2_k  = (const float*)d_in[18];
    const float* p2_v  = (const float*)d_in[19];
    const float* p2_ea = (const float*)d_in[20];
    const float* p2_eb = (const float*)d_in[21];
    const float* p2_em = (const float*)d_in[22];
    const float* p2_g  = (const float*)d_in[23];
    const float* p2_b  = (const float*)d_in[24];
    float* out = (float*)d_out;

    static int smem_set = 0;
    if (!smem_set) {
        cudaFuncSetAttribute(k4_gemm1, cudaFuncAttributeMaxDynamicSharedMemorySize, K4_SMEM);
        cudaFuncSetAttribute(k4_gemm1, cudaFuncAttributePreferredSharedMemoryCarveout,
                             cudaSharedmemCarveoutMaxShared);
        cudaFuncSetAttribute(k5_attn1, cudaFuncAttributeMaxDynamicSharedMemorySize, K5_SMEM);
        cudaFuncSetAttribute(k5_attn1, cudaFuncAttributePreferredSharedMemoryCarveout,
                             cudaSharedmemCarveoutMaxShared);
        cudaFuncSetAttribute(k8_gemm2, cudaFuncAttributeMaxDynamicSharedMemorySize, K8_SMEM);
        smem_set = 1;
    }

    k0_pre<<<17, 256>>>(p0_q, p0_k, p0_v, p0_ea, p0_eb, p0_em,
                        p1_q, p1_k, p1_v, p1_ea, p1_eb, p1_em,
                        p2_q, p2_k, p2_v, p2_ea, p2_eb, p2_em);
    k1_stem0<<<dim3(24, 8, 2), 128>>>(x);
    k3_h1<<<3000, 256>>>(p0_g, p0_b);
    k4_gemm1<<<dim3(94, 6), 256, K4_SMEM>>>();
    k5_attn1<<<dim3(150, 4, 2), 512, K5_SMEM>>>();
    k8_gemm2<<<dim3(95, 2, 2), 256, K8_SMEM>>>(p1_g, p1_b);
    k9_attn2<<<dim3(188, 2), 128>>>();
    k11_final<<<dim3(13, 16, 2), 64>>>(out, p2_g, p2_b);
}

// round 15
// speedup vs baseline: 1.2971x; 1.1480x over previous
#include <cuda_runtime.h>
#include <cuda_bf16.h>
#include <cuda_fp16.h>
#include <math.h>
#include <stdint.h>

// ---------------------------------------------------------------------------
// Static device scratch
// ---------------------------------------------------------------------------
__device__ float d_g0[5*12000];
__device__ __nv_bfloat16 d_h1h[12000*64];
__device__ __nv_bfloat16 d_h1l[12000*64];
__device__ __half d_h1f[12000*64];              // h1 in fp16 (for V blocks)
__device__ float d_qk1[2*6*1504*256];           // q cols 0..127, k cols 128..255 (fp32)
__device__ __half d_v1[2*6*1504*512];           // v cols (o*4+m) in fp16
__device__ float d_o1raw[2*2*750*128];
__device__ float d_qkv2[2*2*754*96];            // v cols = 32+o*4+m
__device__ float d_out2[2*750*16];

__device__ __nv_bfloat16 d_W1bh[768*64];        // [n][k] bf16 hi (q/k cols)
__device__ __nv_bfloat16 d_W1bl[768*64];        // lo
__device__ __half d_W1f[512*64];                // V cols only, fp16, [n-256][k]
__device__ float d_Wcat2[128*96];
__device__ float d_Weff0[5*64];
__device__ float d_emb1[4*10];
__device__ float d_emb2[4*10];
__device__ float d_C0;

// contiguous stats block, zeroed by k0 block 16
__device__ float d_stats[318];
#define P_S0     (d_stats)
#define P_SUM1   (d_stats + 30)
#define P_SUMSQ1 (d_stats + 158)
#define P_SUM2   (d_stats + 286)
#define P_SUMSQ2 (d_stats + 302)

__device__ __forceinline__ void mma_bf16(float4& c,
    uint32_t a0, uint32_t a1, uint32_t a2, uint32_t a3,
    uint32_t b0, uint32_t b1)
{
    asm volatile(
        "mma.sync.aligned.m16n8k16.row.col.f32.bf16.bf16.f32 "
        "{%0,%1,%2,%3},{%4,%5,%6,%7},{%8,%9},{%0,%1,%2,%3};"
        : "+f"(c.x), "+f"(c.y), "+f"(c.z), "+f"(c.w)
        : "r"(a0), "r"(a1), "r"(a2), "r"(a3), "r"(b0), "r"(b1));
}

__device__ __forceinline__ void mma_fp16(float4& c,
    uint32_t a0, uint32_t a1, uint32_t a2, uint32_t a3,
    uint32_t b0, uint32_t b1)
{
    asm volatile(
        "mma.sync.aligned.m16n8k16.row.col.f32.f16.f16.f32 "
        "{%0,%1,%2,%3},{%4,%5,%6,%7},{%8,%9},{%0,%1,%2,%3};"
        : "+f"(c.x), "+f"(c.y), "+f"(c.z), "+f"(c.w)
        : "r"(a0), "r"(a1), "r"(a2), "r"(a3), "r"(b0), "r"(b1));
}

__device__ __forceinline__ void ldsm_x4(uint32_t& r0, uint32_t& r1, uint32_t& r2, uint32_t& r3,
                                        uint32_t addr)
{
    asm volatile("ldmatrix.sync.aligned.m8n8.x4.shared.b16 {%0,%1,%2,%3}, [%4];"
        : "=r"(r0), "=r"(r1), "=r"(r2), "=r"(r3) : "r"(addr));
}

// ---------------------------------------------------------------------------
// K0: grid 17. Blocks 0..15: weight conversion. Block 16: embeds/stats.
// ---------------------------------------------------------------------------
__global__ void k0_pre(const float* p0_q, const float* p0_k, const float* p0_v,
                       const float* p0_ea, const float* p0_eb, const float* p0_em,
                       const float* p1_q, const float* p1_k, const float* p1_v,
                       const float* p1_ea, const float* p1_eb, const float* p1_em,
                       const float* p2_q, const float* p2_k, const float* p2_v,
                       const float* p2_ea, const float* p2_eb, const float* p2_em)
{
    int t = threadIdx.x;
    int blk = blockIdx.x;

    if (blk < 16) {
        #pragma unroll
        for (int u = 0; u < 12; u++) {
            int idx = blk*3072 + u*256 + t;
            int j = idx / 64, c = idx % 64;
            float v;
            if (j < 128)       v = p1_q[c*128 + j];
            else if (j < 256)  v = p1_k[c*128 + (j-128)];
            else { int o = (j-256) >> 2, m = (j-256) & 3; v = p1_v[(m*64+c)*128 + o]; }
            __nv_bfloat16 hi = __float2bfloat16_rn(v);
            d_W1bh[idx] = hi;
            d_W1bl[idx] = __float2bfloat16_rn(v - __bfloat162float(hi));
            if (j >= 256) d_W1f[(j-256)*64 + c] = __float2half_rn(v);
        }
        #pragma unroll
        for (int u = 0; u < 3; u++) {
            int idx = blk*768 + u*256 + t;
            int c = idx / 96, j = idx % 96;
            float v;
            if (j < 16)       v = p2_q[c*16 + j];
            else if (j < 32)  v = p2_k[c*16 + (j-16)];
            else { int o = (j-32) >> 2, m = (j-32) & 3; v = p2_v[(m*128+c)*16 + o]; }
            d_Wcat2[idx] = v;
        }
        return;
    }

    for (int i = t; i < 318; i += 256) d_stats[i] = 0.f;

    __shared__ float logit0[4][5], logit1[4][10], logit2[4][10];
    __shared__ float emb0s[4][5];

    if (t == 0) {
        float s = 0.f;
        for (int o = 0; o < 64; o++) s += p0_q[o] * p0_k[o];
        d_C0 = s;
    }
    if (t >= 128 && t < 148) {
        int u = t - 128; int m = u / 5, j = u % 5;
        float la = 0.f, lb = 0.f;
        for (int o = 0; o < 64; o++) {
            la += p0_em[m*64+o] * p0_ea[o];
            lb += p0_em[m*64+o] * p0_eb[o*5+j];
        }
        logit0[m][j] = la + lb;
    }
    if (t < 40) {
        int m = t / 10, kl = t % 10, i = kl / 5, j = kl % 5;
        float la = 0.f, lb = 0.f;
        for (int o = 0; o < 128; o++) {
            la += p1_em[m*128+o] * p1_ea[o*2+i];
            lb += p1_em[m*128+o] * p1_eb[o*5+j];
        }
        logit1[m][kl] = la + lb;
    }
    if (t >= 64 && t < 104) {
        int u = t - 64; int m = u / 10, kl = u % 10, i = kl / 5, j = kl % 5;
        float la = 0.f, lb = 0.f;
        for (int o = 0; o < 16; o++) {
            la += p2_em[m*16+o] * p2_ea[o*2+i];
            lb += p2_em[m*16+o] * p2_eb[o*5+j];
        }
        logit2[m][kl] = la + lb;
    }
    __syncthreads();
    if (t < 5) {
        float mx = -1e30f;
        for (int m = 0; m < 4; m++) mx = fmaxf(mx, logit0[m][t]);
        float e[4], s = 0.f;
        for (int m = 0; m < 4; m++) { e[m] = __expf(logit0[m][t]-mx); s += e[m]; }
        for (int m = 0; m < 4; m++) emb0s[m][t] = e[m] / s;
    }
    if (t >= 32 && t < 42) {
        int kl = t - 32;
        float mx = -1e30f;
        for (int m = 0; m < 4; m++) mx = fmaxf(mx, logit1[m][kl]);
        float e[4], s = 0.f;
        for (int m = 0; m < 4; m++) { e[m] = __expf(logit1[m][kl]-mx); s += e[m]; }
        for (int m = 0; m < 4; m++) d_emb1[m*10+kl] = e[m] / s;
    }
    if (t >= 64 && t < 74) {
        int kl = t - 64;
        float mx = -1e30f;
        for (int m = 0; m < 4; m++) mx = fmaxf(mx, logit2[m][kl]);
        float e[4], s = 0.f;
        for (int m = 0; m < 4; m++) { e[m] = __expf(logit2[m][kl]-mx); s += e[m]; }
        for (int m = 0; m < 4; m++) d_emb2[m*10+kl] = e[m] / s;
    }
    __syncthreads();
    for (int idx = t; idx < 5*64; idx += blockDim.x) {
        int l = idx / 64, o = idx % 64;
        float s = 0.f;
        for (int m = 0; m < 4; m++) s += emb0s[m][l] * p0_v[m*64+o];
        d_Weff0[idx] = s;
    }
}

// ---------------------------------------------------------------------------
// K1: stage0 attention -> g[5] + low-rank BN stats + pad zero-fill.
// grid (24,8,2), block 128
// ---------------------------------------------------------------------------
__global__ void k1_stem0(const float* x)
{
    int tid = threadIdx.x;
    int w = blockIdx.x * 128 + tid;
    int h = blockIdx.y, b = blockIdx.z;
    bool valid = (w < 3000);

    {
        int blockId = (blockIdx.z * 8 + blockIdx.y) * 24 + blockIdx.x;
        #pragma unroll
        for (int u = 0; u < 4; u++) {
            int idx = (blockId * 4 + u) * 128 + tid;
            if (idx < 192512) {
                int fidx = idx * 4;
                int row = fidx >> 8, col = fidx & 255;
                int bb = row >= 1504; int wp = row - bb*1504;
                *(float4*)&d_qk1[((size_t)(bb*9024 + wp))*256 + col] =
                    make_float4(0.f,0.f,0.f,0.f);
                int eidx = idx * 8;
                int vrow = eidx >> 9, vcol = eidx & 511;
                int b2 = vrow >= 1504; int wp2 = vrow - b2*1504;
                *(uint4*)&d_v1[((size_t)(b2*9024 + wp2))*512 + vcol] =
                    make_uint4(0,0,0,0);
            }
        }
    }

    float g[5] = {0.f,0.f,0.f,0.f,0.f};
    if (valid) {
        const float* xr = x + (b*8 + h) * 3000;
        float xc = xr[w];
        float C0 = d_C0;
        float xl[5], sc[5];
        float mx = -1e30f;
        #pragma unroll
        for (int l = 0; l < 5; l++) {
            int c = w + l - 2;
            xl[l] = (c >= 0 && c < 3000) ? xr[c] : 0.f;
            sc[l] = xc * xl[l] * C0;
            mx = fmaxf(mx, sc[l]);
        }
        float s = 0.f;
        #pragma unroll
        for (int l = 0; l < 5; l++) { sc[l] = __expf(sc[l]-mx); s += sc[l]; }
        float inv = 1.f / s;
        #pragma unroll
        for (int l = 0; l < 5; l++) g[l] = sc[l] * inv * xl[l];
    }

    float st[20];
    {
        int si = 0;
        #pragma unroll
        for (int l = 0; l < 5; l++) st[si++] = g[l];
        #pragma unroll
        for (int l = 0; l < 5; l++)
            #pragma unroll
            for (int l2 = l; l2 < 5; l2++) st[si++] = g[l]*g[l2];
    }
    #pragma unroll
    for (int i = 0; i < 20; i++)
        #pragma unroll
        for (int off = 16; off; off >>= 1)
            st[i] += __shfl_xor_sync(0xffffffffu, st[i], off);

    __shared__ float red[4][20];
    int lane = tid & 31, wrp = tid >> 5;
    if (lane == 0)
        for (int i = 0; i < 20; i++) red[wrp][i] = st[i];
    __syncthreads();
    if (tid < 20) {
        float v = red[0][tid] + red[1][tid] + red[2][tid] + red[3][tid];
        int slot;
        if (tid < 5) slot = tid;
        else {
            int k = tid - 5, l = 0;
            while (k >= 5 - l) { k -= 5 - l; l++; }
            slot = 5 + l*5 + (l + k);
        }
        atomicAdd(&P_S0[slot], v);
    }

    if (valid && !(h & 1) && !(w & 1)) {
        int p = b*6000 + (h>>1)*1500 + (w>>1);
        #pragma unroll
        for (int l = 0; l < 5; l++) d_g0[l*12000 + p] = g[l];
    }
}

// ---------------------------------------------------------------------------
// K3: stage0 BN + ReLU -> h1 bf16 hi/lo + fp16. grid 3000, block 256
// ---------------------------------------------------------------------------
__global__ void k3_h1(const float* g0, const float* b0)
{
    __shared__ float sW[5*64];
    __shared__ float sScale[64], sShift[64];
    int tid = threadIdx.x;
    for (int i = tid; i < 320; i += 256) sW[i] = d_Weff0[i];
    __syncthreads();
    if (tid < 64) {
        int c = tid;
        float Wc[5];
        #pragma unroll
        for (int l = 0; l < 5; l++) Wc[l] = sW[l*64 + c];
        float mn = 0.f, mq = 0.f;
        #pragma unroll
        for (int l = 0; l < 5; l++) {
            mn += P_S0[l] * Wc[l];
            #pragma unroll
            for (int l2 = 0; l2 < 5; l2++) {
                int lo = l < l2 ? l : l2, hi = l < l2 ? l2 : l;
                mq += P_S0[5 + lo*5 + hi] * Wc[l] * Wc[l2];
            }
        }
        float n = 48000.f;
        float mean = mn / n;
        float var  = mq / n - mean*mean;
        float sc = g0[c] * rsqrtf(var + 1e-5f);
        sScale[c] = sc;
        sShift[c] = b0[c] - mean * sc;
    }
    __syncthreads();

    int c = tid & 63;
    int p = blockIdx.x * 4 + (tid >> 6);
    float a = 0.f;
    #pragma unroll
    for (int l = 0; l < 5; l++) a += d_g0[l*12000 + p] * sW[l*64 + c];
    float y = fmaxf(fmaf(a, sScale[c], sShift[c]), 0.f);
    __nv_bfloat16 hi = __float2bfloat16_rn(y);
    d_h1h[p*64 + c] = hi;
    d_h1l[p*64 + c] = __float2bfloat16_rn(y - __bfloat162float(hi));
    d_h1f[p*64 + c] = __float2half_rn(y);
}

// ---------------------------------------------------------------------------
// K4: stage1 qkv GEMM (real rows, M'=12032). grid (94, 8), block 256.
// y=0..3: q/k cols, BN=64, 3-term bf16 (fp32 out).
// y=4..7: V cols, BN=128, single-term fp16 (fp16 out).
// ---------------------------------------------------------------------------
#define K4_SMEM ((128*72 + 128*72 + 128*72 + 128*72) * 2)

__global__ void __launch_bounds__(256) k4_gemm1()
{
    extern __shared__ __nv_bfloat16 sh[];
    int tid = threadIdx.x;
    int rowBase = blockIdx.x * 128;
    bool isQK = (blockIdx.y < 4);

    int lane = tid & 31, wid = tid >> 5;
    int g = lane >> 2, tg = lane & 3;
    int mr = (wid >> 1) * 32;

    int arow = (lane < 16) ? lane : (lane - 16);
    int acol = (lane < 16) ? 0 : 8;
    int brow = (lane & 7) + ((lane >> 4) << 3);
    int bcol = ((lane >> 3) & 1) * 8;

    if (isQK) {
        int colBase = blockIdx.y * 64;    // 0,64,128,192
        int ncol = (wid & 1) * 32;

        __nv_bfloat16* Ah = sh;               // [128][72]
        __nv_bfloat16* Al = Ah + 128*72;
        __nv_bfloat16* Bh = Al + 128*72;      // [64 n][72 k]
        __nv_bfloat16* Bl = Bh + 64*72;

        // A tile staging (hi/lo)
        {
            int r = tid >> 1;
            int half = (tid & 1) * 32;
            int prow = rowBase + r;
            int b = prow / 6016; int rem = prow % 6016;
            int hp = 1 + rem / 1504; int wp = rem % 1504;
            bool valid = (wp >= 2 && wp < 1502);
            __nv_bfloat16* dh = Ah + r*72 + half;
            __nv_bfloat16* dl = Al + r*72 + half;
            if (valid) {
                int pos = ((b*4 + (hp-1))*1500 + (wp-2))*64 + half;
                const uint4* sH = (const uint4*)(d_h1h + pos);
                const uint4* sL = (const uint4*)(d_h1l + pos);
                #pragma unroll
                for (int u = 0; u < 4; u++) {
                    ((uint4*)dh)[u] = sH[u];
                    ((uint4*)dl)[u] = sL[u];
                }
            } else {
                uint4 z = make_uint4(0,0,0,0);
                #pragma unroll
                for (int u = 0; u < 4; u++) { ((uint4*)dh)[u] = z; ((uint4*)dl)[u] = z; }
            }
        }
        // B tile staging: 64 rows, 4 threads/row, 16 elems each
        {
            int n = tid >> 2;
            int seg = (tid & 3) * 16;
            const uint4* sH = (const uint4*)(d_W1bh + (colBase + n)*64 + seg);
            const uint4* sL = (const uint4*)(d_W1bl + (colBase + n)*64 + seg);
            uint4* dh = (uint4*)(Bh + n*72 + seg);
            uint4* dl = (uint4*)(Bl + n*72 + seg);
            dh[0] = sH[0]; dh[1] = sH[1];
            dl[0] = sL[0]; dl[1] = sL[1];
        }
        __syncthreads();

        uint32_t aAddrH[2], aAddrL[2];
        #pragma unroll
        for (int mt = 0; mt < 2; mt++) {
            aAddrH[mt] = (uint32_t)__cvta_generic_to_shared(Ah + (mr + mt*16 + arow)*72 + acol);
            aAddrL[mt] = (uint32_t)__cvta_generic_to_shared(Al + (mr + mt*16 + arow)*72 + acol);
        }
        uint32_t bAddrH[2], bAddrL[2];
        #pragma unroll
        for (int pr = 0; pr < 2; pr++) {
            bAddrH[pr] = (uint32_t)__cvta_generic_to_shared(Bh + (ncol + pr*16 + brow)*72 + bcol);
            bAddrL[pr] = (uint32_t)__cvta_generic_to_shared(Bl + (ncol + pr*16 + brow)*72 + bcol);
        }

        float4 acc[2][4];
        #pragma unroll
        for (int i = 0; i < 2; i++)
            #pragma unroll
            for (int j = 0; j < 4; j++) acc[i][j] = make_float4(0.f,0.f,0.f,0.f);

        #pragma unroll
        for (int ks = 0; ks < 4; ks++) {
            uint32_t koff = ks * 32;
            uint32_t ah[2][4], al[2][4];
            #pragma unroll
            for (int mt = 0; mt < 2; mt++) {
                ldsm_x4(ah[mt][0],ah[mt][1],ah[mt][2],ah[mt][3], aAddrH[mt] + koff);
                ldsm_x4(al[mt][0],al[mt][1],al[mt][2],al[mt][3], aAddrL[mt] + koff);
            }
            #pragma unroll
            for (int pr = 0; pr < 2; pr++) {
                uint32_t bh0,bh1,bh2,bh3, bl0,bl1,bl2,bl3;
                ldsm_x4(bh0,bh1,bh2,bh3, bAddrH[pr] + koff);
                ldsm_x4(bl0,bl1,bl2,bl3, bAddrL[pr] + koff);
                #pragma unroll
                for (int mt = 0; mt < 2; mt++) {
                    mma_bf16(acc[mt][2*pr  ], ah[mt][0],ah[mt][1],ah[mt][2],ah[mt][3], bh0,bh1);
                    mma_bf16(acc[mt][2*pr  ], ah[mt][0],ah[mt][1],ah[mt][2],ah[mt][3], bl0,bl1);
                    mma_bf16(acc[mt][2*pr  ], al[mt][0],al[mt][1],al[mt][2],al[mt][3], bh0,bh1);
                    mma_bf16(acc[mt][2*pr+1], ah[mt][0],ah[mt][1],ah[mt][2],ah[mt][3], bh2,bh3);
                    mma_bf16(acc[mt][2*pr+1], ah[mt][0],ah[mt][1],ah[mt][2],ah[mt][3], bl2,bl3);
                    mma_bf16(acc[mt][2*pr+1], al[mt][0],al[mt][1],al[mt][2],al[mt][3], bh2,bh3);
                }
            }
        }

        #pragma unroll
        for (int mt = 0; mt < 2; mt++) {
            #pragma unroll
            for (int half = 0; half < 2; half++) {
                int prow = rowBase + mr + mt*16 + half*8 + g;
                int b = prow / 6016; int rem = prow % 6016;
                int hp = 1 + rem / 1504; int wp = rem % 1504;
                size_t orow = (size_t)(b*6 + hp)*1504 + wp;
                #pragma unroll
                for (int j = 0; j < 4; j++) {
                    int col = colBase + ncol + j*8 + tg*2;
                    float2 v = half ? make_float2(acc[mt][j].z, acc[mt][j].w)
                                    : make_float2(acc[mt][j].x, acc[mt][j].y);
                    *(float2*)&d_qk1[orow*256 + col] = v;
                }
            }
        }
    } else {
        int vcolBase = (blockIdx.y - 4) * 128;  // 0..383
        int ncol = (wid & 1) * 64;

        __half* Af = (__half*)sh;             // [128][72]
        __half* Bf = Af + 128*72;             // [128 n][72 k]

        {
            int r = tid >> 1;
            int half = (tid & 1) * 32;
            int prow = rowBase + r;
            int b = prow / 6016; int rem = prow % 6016;
            int hp = 1 + rem / 1504; int wp = rem % 1504;
            bool valid = (wp >= 2 && wp < 1502);
            __half* df = Af + r*72 + half;
            if (valid) {
                int pos = ((b*4 + (hp-1))*1500 + (wp-2))*64 + half;
                const uint4* sF = (const uint4*)(d_h1f + pos);
                #pragma unroll
                for (int u = 0; u < 4; u++) ((uint4*)df)[u] = sF[u];
            } else {
                uint4 z = make_uint4(0,0,0,0);
                #pragma unroll
                for (int u = 0; u < 4; u++) ((uint4*)df)[u] = z;
            }
        }
        {
            int n = tid >> 1;
            int seg = (tid & 1) * 32;
            const uint4* sF = (const uint4*)(d_W1f + (vcolBase + n)*64 + seg);
            uint4* df = (uint4*)(Bf + n*72 + seg);
            #pragma unroll
            for (int u = 0; u < 4; u++) df[u] = sF[u];
        }
        __syncthreads();

        uint32_t aAddr[2];
        #pragma unroll
        for (int mt = 0; mt < 2; mt++)
            aAddr[mt] = (uint32_t)__cvta_generic_to_shared(Af + (mr + mt*16 + arow)*72 + acol);
        uint32_t bAddr[4];
        #pragma unroll
        for (int pr = 0; pr < 4; pr++)
            bAddr[pr] = (uint32_t)__cvta_generic_to_shared(Bf + (ncol + pr*16 + brow)*72 + bcol);

        float4 acc[2][8];
        #pragma unroll
        for (int i = 0; i < 2; i++)
            #pragma unroll
            for (int j = 0; j < 8; j++) acc[i][j] = make_float4(0.f,0.f,0.f,0.f);

        #pragma unroll
        for (int ks = 0; ks < 4; ks++) {
            uint32_t koff = ks * 32;
            uint32_t af[2][4];
            #pragma unroll
            for (int mt = 0; mt < 2; mt++)
                ldsm_x4(af[mt][0],af[mt][1],af[mt][2],af[mt][3], aAddr[mt] + koff);
            #pragma unroll
            for (int pr = 0; pr < 4; pr++) {
                uint32_t b0,b1,b2,b3;
                ldsm_x4(b0,b1,b2,b3, bAddr[pr] + koff);
                #pragma unroll
                for (int mt = 0; mt < 2; mt++) {
                    mma_fp16(acc[mt][2*pr  ], af[mt][0],af[mt][1],af[mt][2],af[mt][3], b0,b1);
                    mma_fp16(acc[mt][2*pr+1], af[mt][0],af[mt][1],af[mt][2],af[mt][3], b2,b3);
                }
            }
        }

        #pragma unroll
        for (int mt = 0; mt < 2; mt++) {
            #pragma unroll
            for (int half = 0; half < 2; half++) {
                int prow = rowBase + mr + mt*16 + half*8 + g;
                int b = prow / 6016; int rem = prow % 6016;
                int hp = 1 + rem / 1504; int wp = rem % 1504;
                size_t orow = (size_t)(b*6 + hp)*1504 + wp;
                #pragma unroll
                for (int j = 0; j < 8; j++) {
                    int col = vcolBase + ncol + j*8 + tg*2;
                    float2 v = half ? make_float2(acc[mt][j].z, acc[mt][j].w)
                                    : make_float2(acc[mt][j].x, acc[mt][j].y);
                    __half2 hv;
                    hv.x = __float2half_rn(v.x);
                    hv.y = __float2half_rn(v.y);
                    *(__half2*)&d_v1[orow*512 + col] = hv;
                }
            }
        }
    }
}

// ---------------------------------------------------------------------------
// K5: stage1 attention combine, 15 positions/block, 512 threads.
// grid (100, 4, 2). kv window rows jj in [0,19) per i (w0+18 <= 1503).
// smem: sq[15][128]f + sk[38][128]f + sv[38][512]h = 66048 B
// ---------------------------------------------------------------------------
#define K5_SMEM ((15*128 + 38*128) * 4 + 38*512*2)

__global__ void k5_attn1()
{
    extern __shared__ float sm5[];
    float* sq = sm5;                               // [15][128]
    float* sk = sm5 + 15*128;                      // [38][128] r=i*19+jj
    __half* sv = (__half*)(sm5 + 15*128 + 38*128); // [38][512]

    int w0 = blockIdx.x * 15, h = blockIdx.y, b = blockIdx.z;
    int tid = threadIdx.x, lane = tid & 31, wrp = tid >> 5;  // 16 warps
    __shared__ float ssc[15][10];
    __shared__ float cm4[15][40];

    const float* qkbase = d_qk1 + (size_t)b * 6 * 1504 * 256;
    const __half* vbase = d_v1 + (size_t)b * 6 * 1504 * 512;

    // stage q: 15 rows x 32 float4 = 480
    for (int idx = tid; idx < 480; idx += 512) {
        int p = idx >> 5, c4 = idx & 31;
        ((float4*)sq)[p*32 + c4] =
            *(const float4*)(qkbase + ((h+1)*1504 + (w0+2+p))*256 + c4*4);
    }
    // stage k: 38 rows x 32 float4 = 1216
    for (int idx = tid; idx < 1216; idx += 512) {
        int r = idx >> 5, c4 = idx & 31;
        int i = r / 19, jj = r % 19;
        ((float4*)(sk + r*128))[c4] =
            *(const float4*)(qkbase + ((h+i)*1504 + (w0+jj))*256 + 128 + c4*4);
    }
    // stage v: 38 rows x 64 uint4 = 2432
    for (int idx = tid; idx < 2432; idx += 512) {
        int r = idx >> 6, c4 = idx & 63;
        int i = r / 19, jj = r % 19;
        ((uint4*)(sv + r*512))[c4] =
            *(const uint4*)(vbase + ((h+i)*1504 + (w0+jj))*512 + c4*8);
    }
    __syncthreads();

    // scores: 150 (p,kl) pairs over 16 warps
    for (int pair = wrp; pair < 150; pair += 16) {
        int p = pair / 10, kl = pair % 10;
        int i = kl / 5, j = kl % 5;
        float4 q4 = ((const float4*)(sq + p*128))[lane];
        float4 k4 = ((const float4*)(sk + (i*19 + p + j)*128))[lane];
        float s = q4.x*k4.x + q4.y*k4.y + q4.z*k4.z + q4.w*k4.w;
        #pragma unroll
        for (int off = 16; off; off >>= 1) s += __shfl_xor_sync(0xffffffffu, s, off);
        if (lane == 0) ssc[p][kl] = s;
    }
    __syncthreads();
    if (tid < 15) {
        float mx = -1e30f;
        #pragma unroll
        for (int kl = 0; kl < 10; kl++) mx = fmaxf(mx, ssc[tid][kl]);
        float e[10], s = 0.f;
        #pragma unroll
        for (int kl = 0; kl < 10; kl++) { e[kl] = __expf(ssc[tid][kl]-mx); s += e[kl]; }
        float inv = 1.f / s;
        #pragma unroll
        for (int kl = 0; kl < 10; kl++) {
            float a = e[kl] * inv;
            #pragma unroll
            for (int m = 0; m < 4; m++) cm4[tid][kl*4+m] = a * d_emb1[m*10+kl];
        }
    }
    __syncthreads();

    int o = tid & 127;
    int ph = tid >> 7;    // 0..3
    float s1 = 0.f, s2 = 0.f;
    for (int p = ph; p < 15; p += 4) {
        const float* cw = cm4[p];
        float acc = 0.f;
        #pragma unroll
        for (int kl = 0; kl < 10; kl++) {
            int i = kl / 5, j = kl % 5;
            uint2 pv = *(const uint2*)(sv + (i*19 + p + j)*512 + o*4);
            float2 v01 = __half22float2(*(const __half2*)&pv.x);
            float2 v23 = __half22float2(*(const __half2*)&pv.y);
            acc += cw[kl*4]*v01.x + cw[kl*4+1]*v01.y + cw[kl*4+2]*v23.x + cw[kl*4+3]*v23.y;
        }
        s1 += acc; s2 += acc*acc;
        if (!(h & 1) && !((w0+p) & 1))
            d_o1raw[((b*2 + (h>>1))*750 + ((w0+p)>>1))*128 + o] = acc;
    }
    atomicAdd(&P_SUM1[o], s1);
    atomicAdd(&P_SUMSQ1[o], s2);
}

// ---------------------------------------------------------------------------
// K8: stage2 qkv GEMM, ILP-split dots, 8 positions/block.
// grid (95, 2, 2), block 256.
// ---------------------------------------------------------------------------
#define K8_SMEM ((128*96 + 8*128) * 4)

__global__ void k8_gemm2(const float* g1, const float* b1)
{
    extern __shared__ float sm8[];
    float* sWt = sm8;               // [128][96]
    float* sa  = sm8 + 128*96;      // [8][128]
    __shared__ float sScale[128], sShift[128];

    int t = threadIdx.x;
    int hp = blockIdx.y, b = blockIdx.z;
    int W0 = blockIdx.x * 8;

    if (t < 128) {
        float n = 12000.f;
        float mean = P_SUM1[t] / n;
        float var  = P_SUMSQ1[t] / n - mean*mean;
        float sc = g1[t] * rsqrtf(var + 1e-5f);
        sScale[t] = sc;
        sShift[t] = b1[t] - mean*sc;
    }
    for (int idx = t; idx < 3072; idx += 256)
        ((float4*)sWt)[idx] = ((const float4*)d_Wcat2)[idx];
    __syncthreads();

    for (int idx = t; idx < 1024; idx += 256) {
        int ps = idx >> 7, i = idx & 127;
        int wp = W0 + ps;
        float v = 0.f;
        if (wp >= 2 && wp < 752) {
            float raw = d_o1raw[(((b*2 + hp)*750) + (wp-2))*128 + i];
            v = fmaxf(fmaf(raw, sScale[i], sShift[i]), 0.f);
        }
        sa[ps*128 + i] = v;
    }
    __syncthreads();

    #pragma unroll
    for (int k = 0; k < 3; k++) {
        int pair = t + k*256;
        int ps = pair / 96, o = pair - (pair/96)*96;
        int wp = W0 + ps;
        if (wp >= 754) continue;
        const float* av = sa + ps*128;
        float a0 = 0.f, a1 = 0.f, a2 = 0.f, a3 = 0.f;
        #pragma unroll
        for (int c = 0; c < 32; c++) {
            a0 = fmaf(av[c],     sWt[c*96 + o],        a0);
            a1 = fmaf(av[c+32],  sWt[(c+32)*96 + o],   a1);
            a2 = fmaf(av[c+64],  sWt[(c+64)*96 + o],   a2);
            a3 = fmaf(av[c+96],  sWt[(c+96)*96 + o],   a3);
        }
        d_qkv2[(((b*2 + hp)*754) + wp)*96 + o] = (a0 + a1) + (a2 + a3);
    }
}

// ---------------------------------------------------------------------------
// K9: stage2 attention combine, warp per position. grid (188, 2), block 128
// ---------------------------------------------------------------------------
__global__ void k9_attn2()
{
    __shared__ float semb[40];
    int tid = threadIdx.x;
    if (tid < 40) { int kl = tid >> 2, m = tid & 3; semb[tid] = d_emb2[m*10+kl]; }
    __syncthreads();

    int lane = tid & 31, wrp = tid >> 5;
    int w = blockIdx.x * 4 + wrp, b = blockIdx.y;
    if (w >= 750) return;

    const float* base = d_qkv2 + (size_t)b * 2 * 754 * 96;
    const float* qp = base + (w + 2) * 96;
    float qv = (lane < 16) ? qp[lane] : 0.f;

    float scl[10];
    float mx = -1e30f;
    #pragma unroll
    for (int kl = 0; kl < 10; kl++) {
        int i = kl / 5, j = kl % 5;
        const float* kp = base + (i*754 + (w+j))*96 + 16;
        float pr = (lane < 16) ? qv * kp[lane] : 0.f;
        #pragma unroll
        for (int off = 8; off; off >>= 1) pr += __shfl_xor_sync(0xffffffffu, pr, off);
        scl[kl] = pr;
        mx = fmaxf(mx, pr);
    }
    float s = 0.f;
    #pragma unroll
    for (int kl = 0; kl < 10; kl++) { scl[kl] = __expf(scl[kl]-mx); s += scl[kl]; }
    float inv = 1.f / s;
    if (lane < 16) {
        float acc = 0.f;
        #pragma unroll
        for (int kl = 0; kl < 10; kl++) {
            int i = kl / 5, j = kl % 5;
            float4 v = *(const float4*)(base + (i*754 + (w+j))*96 + 32 + lane*4);
            float aw = scl[kl] * inv;
            acc += aw * (semb[kl*4]*v.x + semb[kl*4+1]*v.y + semb[kl*4+2]*v.z + semb[kl*4+3]*v.w);
        }
        d_out2[(b*750 + w)*16 + lane] = acc;
        atomicAdd(&P_SUM2[lane], acc);
        atomicAdd(&P_SUMSQ2[lane], acc*acc);
    }
}

// ---------------------------------------------------------------------------
// K11: stage2 BN + ReLU + AvgPool(1,56) -> out. grid (13,16,2), block 64
// ---------------------------------------------------------------------------
__global__ void k11_final(float* out, const float* g2, const float* b2)
{
    int n = blockIdx.x, c = blockIdx.y, b = blockIdx.z;
    int t = threadIdx.x;
    float nn = 1500.f;
    float mean = P_SUM2[c] / nn;
    float var  = P_SUMSQ2[c] / nn - mean*mean;
    float sc = g2[c] * rsqrtf(var + 1e-5f);
    float sf = b2[c] - mean * sc;

    float v = 0.f;
    if (t < 56) {
        float raw = d_out2[(b*750 + n*56 + t)*16 + c];
        v = fmaxf(fmaf(raw, sc, sf), 0.f);
    }
    __shared__ float shm[64];
    shm[t] = v;
    __syncthreads();
    for (int st = 32; st; st >>= 1) {
        if (t < st) shm[t] += shm[t+st];
        __syncthreads();
    }
    if (t == 0) out[(b*16 + c)*13 + n] = shm[0] * (1.f/56.f);
}

// ---------------------------------------------------------------------------
extern "C" void kernel_launch(void* const* d_in, const int* in_sizes, int n_in,
                              void* d_out, int out_size)
{
    const float* x     = (const float*)d_in[0];
    const float* p0_q  = (const float*)d_in[1];
    const float* p0_k  = (const float*)d_in[2];
    const float* p0_v  = (const float*)d_in[3];
    const float* p0_ea = (const float*)d_in[4];
    const float* p0_eb = (const float*)d_in[5];
    const float* p0_em = (const float*)d_in[6];
    const float* p0_g  = (const float*)d_in[7];
    const float* p0_b  = (const float*)d_in[8];
    const float* p1_q  = (const float*)d_in[9];
    const float* p1_k  = (const float*)d_in[10];
    const float* p1_v  = (const float*)d_in[11];
    const float* p1_ea = (const float*)d_in[12];
    const float* p1_eb = (const float*)d_in[13];
    const float* p1_em = (const float*)d_in[14];
    const float* p1_g  = (const float*)d_in[15];
    const float* p1_b  = (const float*)d_in[16];
    const float* p2_q  = (const float*)d_in[17];
    const float* p2_k  = (const float*)d_in[18];
    const float* p2_v  = (const float*)d_in[19];
    const float* p2_ea = (const float*)d_in[20];
    const float* p2_eb = (const float*)d_in[21];
    const float* p2_em = (const float*)d_in[22];
    const float* p2_g  = (const float*)d_in[23];
    const float* p2_b  = (const float*)d_in[24];
    float* out = (float*)d_out;

    static int smem_set = 0;
    if (!smem_set) {
        cudaFuncSetAttribute(k4_gemm1, cudaFuncAttributeMaxDynamicSharedMemorySize, K4_SMEM);
        cudaFuncSetAttribute(k4_gemm1, cudaFuncAttributePreferredSharedMemoryCarveout,
                             cudaSharedmemCarveoutMaxShared);
        cudaFuncSetAttribute(k5_attn1, cudaFuncAttributeMaxDynamicSharedMemorySize, K5_SMEM);
        cudaFuncSetAttribute(k5_attn1, cudaFuncAttributePreferredSharedMemoryCarveout,
                             cudaSharedmemCarveoutMaxShared);
        cudaFuncSetAttribute(k8_gemm2, cudaFuncAttributeMaxDynamicSharedMemorySize, K8_SMEM);
        smem_set = 1;
    }

    k0_pre<<<17, 256>>>(p0_q, p0_k, p0_v, p0_ea, p0_eb, p0_em,
                        p1_q, p1_k, p1_v, p1_ea, p1_eb, p1_em,
                        p2_q, p2_k, p2_v, p2_ea, p2_eb, p2_em);
    k1_stem0<<<dim3(24, 8, 2), 128>>>(x);
    k3_h1<<<3000, 256>>>(p0_g, p0_b);
    k4_gemm1<<<dim3(94, 8), 256, K4_SMEM>>>();
    k5_attn1<<<dim3(100, 4, 2), 512, K5_SMEM>>>();
    k8_gemm2<<<dim3(95, 2, 2), 256, K8_SMEM>>>(p1_g, p1_b);
    k9_attn2<<<dim3(188, 2), 128>>>();
    k11_final<<<dim3(13, 16, 2), 64>>>(out, p2_g, p2_b);
}

// round 16
// speedup vs baseline: 1.3527x; 1.0429x over previous
#include <cuda_runtime.h>
#include <cuda_bf16.h>
#include <cuda_fp16.h>
#include <math.h>
#include <stdint.h>

// ---------------------------------------------------------------------------
// Static device scratch
// ---------------------------------------------------------------------------
__device__ float d_g0[5*12000];
__device__ __nv_bfloat16 d_h1h[12000*64];
__device__ __nv_bfloat16 d_h1l[12000*64];
__device__ __half d_h1f[12000*64];              // h1 in fp16 (for V blocks)
__device__ float d_qk1[2*6*1504*256];           // q cols 0..127, k cols 128..255 (fp32)
__device__ __half d_v1[2*6*1504*512];           // v cols (o*4+m) in fp16
__device__ float d_o1raw[2*2*750*128];
__device__ float d_qkv2[2*2*754*96];            // v cols = 32+o*4+m
__device__ float d_out2[2*750*16];

__device__ __nv_bfloat16 d_W1bh[768*64];        // [n][k] bf16 hi (q/k cols)
__device__ __nv_bfloat16 d_W1bl[768*64];        // lo
__device__ __half d_W1f[512*64];                // V cols only, fp16, [n-256][k]
__device__ float d_Wcat2[128*96];
__device__ float d_Weff0[5*64];
__device__ float d_emb1[4*10];
__device__ float d_emb2[4*10];
__device__ float d_C0;

// contiguous stats block, zeroed by k0 block 16
__device__ float d_stats[318];
#define P_S0     (d_stats)
#define P_SUM1   (d_stats + 30)
#define P_SUMSQ1 (d_stats + 158)
#define P_SUM2   (d_stats + 286)
#define P_SUMSQ2 (d_stats + 302)

__device__ __forceinline__ void mma_bf16(float4& c,
    uint32_t a0, uint32_t a1, uint32_t a2, uint32_t a3,
    uint32_t b0, uint32_t b1)
{
    asm volatile(
        "mma.sync.aligned.m16n8k16.row.col.f32.bf16.bf16.f32 "
        "{%0,%1,%2,%3},{%4,%5,%6,%7},{%8,%9},{%0,%1,%2,%3};"
        : "+f"(c.x), "+f"(c.y), "+f"(c.z), "+f"(c.w)
        : "r"(a0), "r"(a1), "r"(a2), "r"(a3), "r"(b0), "r"(b1));
}

__device__ __forceinline__ void mma_fp16(float4& c,
    uint32_t a0, uint32_t a1, uint32_t a2, uint32_t a3,
    uint32_t b0, uint32_t b1)
{
    asm volatile(
        "mma.sync.aligned.m16n8k16.row.col.f32.f16.f16.f32 "
        "{%0,%1,%2,%3},{%4,%5,%6,%7},{%8,%9},{%0,%1,%2,%3};"
        : "+f"(c.x), "+f"(c.y), "+f"(c.z), "+f"(c.w)
        : "r"(a0), "r"(a1), "r"(a2), "r"(a3), "r"(b0), "r"(b1));
}

__device__ __forceinline__ void ldsm_x4(uint32_t& r0, uint32_t& r1, uint32_t& r2, uint32_t& r3,
                                        uint32_t addr)
{
    asm volatile("ldmatrix.sync.aligned.m8n8.x4.shared.b16 {%0,%1,%2,%3}, [%4];"
        : "=r"(r0), "=r"(r1), "=r"(r2), "=r"(r3) : "r"(addr));
}

// ---------------------------------------------------------------------------
// K0: grid 17. Blocks 0..15: weight conversion. Block 16: embeds/stats.
// ---------------------------------------------------------------------------
__global__ void k0_pre(const float* p0_q, const float* p0_k, const float* p0_v,
                       const float* p0_ea, const float* p0_eb, const float* p0_em,
                       const float* p1_q, const float* p1_k, const float* p1_v,
                       const float* p1_ea, const float* p1_eb, const float* p1_em,
                       const float* p2_q, const float* p2_k, const float* p2_v,
                       const float* p2_ea, const float* p2_eb, const float* p2_em)
{
    int t = threadIdx.x;
    int blk = blockIdx.x;

    if (blk < 16) {
        #pragma unroll
        for (int u = 0; u < 12; u++) {
            int idx = blk*3072 + u*256 + t;
            int j = idx / 64, c = idx % 64;
            float v;
            if (j < 128)       v = p1_q[c*128 + j];
            else if (j < 256)  v = p1_k[c*128 + (j-128)];
            else { int o = (j-256) >> 2, m = (j-256) & 3; v = p1_v[(m*64+c)*128 + o]; }
            __nv_bfloat16 hi = __float2bfloat16_rn(v);
            d_W1bh[idx] = hi;
            d_W1bl[idx] = __float2bfloat16_rn(v - __bfloat162float(hi));
            if (j >= 256) d_W1f[(j-256)*64 + c] = __float2half_rn(v);
        }
        #pragma unroll
        for (int u = 0; u < 3; u++) {
            int idx = blk*768 + u*256 + t;
            int c = idx / 96, j = idx % 96;
            float v;
            if (j < 16)       v = p2_q[c*16 + j];
            else if (j < 32)  v = p2_k[c*16 + (j-16)];
            else { int o = (j-32) >> 2, m = (j-32) & 3; v = p2_v[(m*128+c)*16 + o]; }
            d_Wcat2[idx] = v;
        }
        return;
    }

    for (int i = t; i < 318; i += 256) d_stats[i] = 0.f;

    __shared__ float logit0[4][5], logit1[4][10], logit2[4][10];
    __shared__ float emb0s[4][5];

    if (t == 0) {
        float s = 0.f;
        for (int o = 0; o < 64; o++) s += p0_q[o] * p0_k[o];
        d_C0 = s;
    }
    if (t >= 128 && t < 148) {
        int u = t - 128; int m = u / 5, j = u % 5;
        float la = 0.f, lb = 0.f;
        for (int o = 0; o < 64; o++) {
            la += p0_em[m*64+o] * p0_ea[o];
            lb += p0_em[m*64+o] * p0_eb[o*5+j];
        }
        logit0[m][j] = la + lb;
    }
    if (t < 40) {
        int m = t / 10, kl = t % 10, i = kl / 5, j = kl % 5;
        float la = 0.f, lb = 0.f;
        for (int o = 0; o < 128; o++) {
            la += p1_em[m*128+o] * p1_ea[o*2+i];
            lb += p1_em[m*128+o] * p1_eb[o*5+j];
        }
        logit1[m][kl] = la + lb;
    }
    if (t >= 64 && t < 104) {
        int u = t - 64; int m = u / 10, kl = u % 10, i = kl / 5, j = kl % 5;
        float la = 0.f, lb = 0.f;
        for (int o = 0; o < 16; o++) {
            la += p2_em[m*16+o] * p2_ea[o*2+i];
            lb += p2_em[m*16+o] * p2_eb[o*5+j];
        }
        logit2[m][kl] = la + lb;
    }
    __syncthreads();
    if (t < 5) {
        float mx = -1e30f;
        for (int m = 0; m < 4; m++) mx = fmaxf(mx, logit0[m][t]);
        float e[4], s = 0.f;
        for (int m = 0; m < 4; m++) { e[m] = __expf(logit0[m][t]-mx); s += e[m]; }
        for (int m = 0; m < 4; m++) emb0s[m][t] = e[m] / s;
    }
    if (t >= 32 && t < 42) {
        int kl = t - 32;
        float mx = -1e30f;
        for (int m = 0; m < 4; m++) mx = fmaxf(mx, logit1[m][kl]);
        float e[4], s = 0.f;
        for (int m = 0; m < 4; m++) { e[m] = __expf(logit1[m][kl]-mx); s += e[m]; }
        for (int m = 0; m < 4; m++) d_emb1[m*10+kl] = e[m] / s;
    }
    if (t >= 64 && t < 74) {
        int kl = t - 64;
        float mx = -1e30f;
        for (int m = 0; m < 4; m++) mx = fmaxf(mx, logit2[m][kl]);
        float e[4], s = 0.f;
        for (int m = 0; m < 4; m++) { e[m] = __expf(logit2[m][kl]-mx); s += e[m]; }
        for (int m = 0; m < 4; m++) d_emb2[m*10+kl] = e[m] / s;
    }
    __syncthreads();
    for (int idx = t; idx < 5*64; idx += blockDim.x) {
        int l = idx / 64, o = idx % 64;
        float s = 0.f;
        for (int m = 0; m < 4; m++) s += emb0s[m][l] * p0_v[m*64+o];
        d_Weff0[idx] = s;
    }
}

// ---------------------------------------------------------------------------
// K1: stage0 attention -> g[5] + low-rank BN stats + pad zero-fill.
// grid (24,8,2), block 128
// ---------------------------------------------------------------------------
__global__ void k1_stem0(const float* x)
{
    int tid = threadIdx.x;
    int w = blockIdx.x * 128 + tid;
    int h = blockIdx.y, b = blockIdx.z;
    bool valid = (w < 3000);

    {
        int blockId = (blockIdx.z * 8 + blockIdx.y) * 24 + blockIdx.x;
        #pragma unroll
        for (int u = 0; u < 4; u++) {
            int idx = (blockId * 4 + u) * 128 + tid;
            if (idx < 192512) {
                int fidx = idx * 4;
                int row = fidx >> 8, col = fidx & 255;
                int bb = row >= 1504; int wp = row - bb*1504;
                *(float4*)&d_qk1[((size_t)(bb*9024 + wp))*256 + col] =
                    make_float4(0.f,0.f,0.f,0.f);
                int eidx = idx * 8;
                int vrow = eidx >> 9, vcol = eidx & 511;
                int b2 = vrow >= 1504; int wp2 = vrow - b2*1504;
                *(uint4*)&d_v1[((size_t)(b2*9024 + wp2))*512 + vcol] =
                    make_uint4(0,0,0,0);
            }
        }
    }

    float g[5] = {0.f,0.f,0.f,0.f,0.f};
    if (valid) {
        const float* xr = x + (b*8 + h) * 3000;
        float xc = xr[w];
        float C0 = d_C0;
        float xl[5], sc[5];
        float mx = -1e30f;
        #pragma unroll
        for (int l = 0; l < 5; l++) {
            int c = w + l - 2;
            xl[l] = (c >= 0 && c < 3000) ? xr[c] : 0.f;
            sc[l] = xc * xl[l] * C0;
            mx = fmaxf(mx, sc[l]);
        }
        float s = 0.f;
        #pragma unroll
        for (int l = 0; l < 5; l++) { sc[l] = __expf(sc[l]-mx); s += sc[l]; }
        float inv = 1.f / s;
        #pragma unroll
        for (int l = 0; l < 5; l++) g[l] = sc[l] * inv * xl[l];
    }

    float st[20];
    {
        int si = 0;
        #pragma unroll
        for (int l = 0; l < 5; l++) st[si++] = g[l];
        #pragma unroll
        for (int l = 0; l < 5; l++)
            #pragma unroll
            for (int l2 = l; l2 < 5; l2++) st[si++] = g[l]*g[l2];
    }
    #pragma unroll
    for (int i = 0; i < 20; i++)
        #pragma unroll
        for (int off = 16; off; off >>= 1)
            st[i] += __shfl_xor_sync(0xffffffffu, st[i], off);

    __shared__ float red[4][20];
    int lane = tid & 31, wrp = tid >> 5;
    if (lane == 0)
        for (int i = 0; i < 20; i++) red[wrp][i] = st[i];
    __syncthreads();
    if (tid < 20) {
        float v = red[0][tid] + red[1][tid] + red[2][tid] + red[3][tid];
        int slot;
        if (tid < 5) slot = tid;
        else {
            int k = tid - 5, l = 0;
            while (k >= 5 - l) { k -= 5 - l; l++; }
            slot = 5 + l*5 + (l + k);
        }
        atomicAdd(&P_S0[slot], v);
    }

    if (valid && !(h & 1) && !(w & 1)) {
        int p = b*6000 + (h>>1)*1500 + (w>>1);
        #pragma unroll
        for (int l = 0; l < 5; l++) d_g0[l*12000 + p] = g[l];
    }
}

// ---------------------------------------------------------------------------
// K3: stage0 BN + ReLU -> h1 bf16 hi/lo + fp16. grid 3000, block 256
// ---------------------------------------------------------------------------
__global__ void k3_h1(const float* g0, const float* b0)
{
    __shared__ float sW[5*64];
    __shared__ float sScale[64], sShift[64];
    int tid = threadIdx.x;
    for (int i = tid; i < 320; i += 256) sW[i] = d_Weff0[i];
    __syncthreads();
    if (tid < 64) {
        int c = tid;
        float Wc[5];
        #pragma unroll
        for (int l = 0; l < 5; l++) Wc[l] = sW[l*64 + c];
        float mn = 0.f, mq = 0.f;
        #pragma unroll
        for (int l = 0; l < 5; l++) {
            mn += P_S0[l] * Wc[l];
            #pragma unroll
            for (int l2 = 0; l2 < 5; l2++) {
                int lo = l < l2 ? l : l2, hi = l < l2 ? l2 : l;
                mq += P_S0[5 + lo*5 + hi] * Wc[l] * Wc[l2];
            }
        }
        float n = 48000.f;
        float mean = mn / n;
        float var  = mq / n - mean*mean;
        float sc = g0[c] * rsqrtf(var + 1e-5f);
        sScale[c] = sc;
        sShift[c] = b0[c] - mean * sc;
    }
    __syncthreads();

    int c = tid & 63;
    int p = blockIdx.x * 4 + (tid >> 6);
    float a = 0.f;
    #pragma unroll
    for (int l = 0; l < 5; l++) a += d_g0[l*12000 + p] * sW[l*64 + c];
    float y = fmaxf(fmaf(a, sScale[c], sShift[c]), 0.f);
    __nv_bfloat16 hi = __float2bfloat16_rn(y);
    d_h1h[p*64 + c] = hi;
    d_h1l[p*64 + c] = __float2bfloat16_rn(y - __bfloat162float(hi));
    d_h1f[p*64 + c] = __float2half_rn(y);
}

// ---------------------------------------------------------------------------
// K4: stage1 qkv GEMM (real rows, M'=12032). grid (94, 8), block 256.
// y=0..3: q/k cols, BN=64, 3-term bf16 (fp32 out).
// y=4..7: V cols, BN=128, single-term fp16 (fp16 out).
// ---------------------------------------------------------------------------
#define K4_SMEM ((128*72 + 128*72 + 128*72 + 128*72) * 2)

__global__ void __launch_bounds__(256) k4_gemm1()
{
    extern __shared__ __nv_bfloat16 sh[];
    int tid = threadIdx.x;
    int rowBase = blockIdx.x * 128;
    bool isQK = (blockIdx.y < 4);

    int lane = tid & 31, wid = tid >> 5;
    int g = lane >> 2, tg = lane & 3;
    int mr = (wid >> 1) * 32;

    int arow = (lane < 16) ? lane : (lane - 16);
    int acol = (lane < 16) ? 0 : 8;
    int brow = (lane & 7) + ((lane >> 4) << 3);
    int bcol = ((lane >> 3) & 1) * 8;

    if (isQK) {
        int colBase = blockIdx.y * 64;
        int ncol = (wid & 1) * 32;

        __nv_bfloat16* Ah = sh;
        __nv_bfloat16* Al = Ah + 128*72;
        __nv_bfloat16* Bh = Al + 128*72;
        __nv_bfloat16* Bl = Bh + 64*72;

        {
            int r = tid >> 1;
            int half = (tid & 1) * 32;
            int prow = rowBase + r;
            int b = prow / 6016; int rem = prow % 6016;
            int hp = 1 + rem / 1504; int wp = rem % 1504;
            bool valid = (wp >= 2 && wp < 1502);
            __nv_bfloat16* dh = Ah + r*72 + half;
            __nv_bfloat16* dl = Al + r*72 + half;
            if (valid) {
                int pos = ((b*4 + (hp-1))*1500 + (wp-2))*64 + half;
                const uint4* sH = (const uint4*)(d_h1h + pos);
                const uint4* sL = (const uint4*)(d_h1l + pos);
                #pragma unroll
                for (int u = 0; u < 4; u++) {
                    ((uint4*)dh)[u] = sH[u];
                    ((uint4*)dl)[u] = sL[u];
                }
            } else {
                uint4 z = make_uint4(0,0,0,0);
                #pragma unroll
                for (int u = 0; u < 4; u++) { ((uint4*)dh)[u] = z; ((uint4*)dl)[u] = z; }
            }
        }
        {
            int n = tid >> 2;
            int seg = (tid & 3) * 16;
            const uint4* sH = (const uint4*)(d_W1bh + (colBase + n)*64 + seg);
            const uint4* sL = (const uint4*)(d_W1bl + (colBase + n)*64 + seg);
            uint4* dh = (uint4*)(Bh + n*72 + seg);
            uint4* dl = (uint4*)(Bl + n*72 + seg);
            dh[0] = sH[0]; dh[1] = sH[1];
            dl[0] = sL[0]; dl[1] = sL[1];
        }
        __syncthreads();

        uint32_t aAddrH[2], aAddrL[2];
        #pragma unroll
        for (int mt = 0; mt < 2; mt++) {
            aAddrH[mt] = (uint32_t)__cvta_generic_to_shared(Ah + (mr + mt*16 + arow)*72 + acol);
            aAddrL[mt] = (uint32_t)__cvta_generic_to_shared(Al + (mr + mt*16 + arow)*72 + acol);
        }
        uint32_t bAddrH[2], bAddrL[2];
        #pragma unroll
        for (int pr = 0; pr < 2; pr++) {
            bAddrH[pr] = (uint32_t)__cvta_generic_to_shared(Bh + (ncol + pr*16 + brow)*72 + bcol);
            bAddrL[pr] = (uint32_t)__cvta_generic_to_shared(Bl + (ncol + pr*16 + brow)*72 + bcol);
        }

        float4 acc[2][4];
        #pragma unroll
        for (int i = 0; i < 2; i++)
            #pragma unroll
            for (int j = 0; j < 4; j++) acc[i][j] = make_float4(0.f,0.f,0.f,0.f);

        #pragma unroll
        for (int ks = 0; ks < 4; ks++) {
            uint32_t koff = ks * 32;
            uint32_t ah[2][4], al[2][4];
            #pragma unroll
            for (int mt = 0; mt < 2; mt++) {
                ldsm_x4(ah[mt][0],ah[mt][1],ah[mt][2],ah[mt][3], aAddrH[mt] + koff);
                ldsm_x4(al[mt][0],al[mt][1],al[mt][2],al[mt][3], aAddrL[mt] + koff);
            }
            #pragma unroll
            for (int pr = 0; pr < 2; pr++) {
                uint32_t bh0,bh1,bh2,bh3, bl0,bl1,bl2,bl3;
                ldsm_x4(bh0,bh1,bh2,bh3, bAddrH[pr] + koff);
                ldsm_x4(bl0,bl1,bl2,bl3, bAddrL[pr] + koff);
                #pragma unroll
                for (int mt = 0; mt < 2; mt++) {
                    mma_bf16(acc[mt][2*pr  ], ah[mt][0],ah[mt][1],ah[mt][2],ah[mt][3], bh0,bh1);
                    mma_bf16(acc[mt][2*pr  ], ah[mt][0],ah[mt][1],ah[mt][2],ah[mt][3], bl0,bl1);
                    mma_bf16(acc[mt][2*pr  ], al[mt][0],al[mt][1],al[mt][2],al[mt][3], bh0,bh1);
                    mma_bf16(acc[mt][2*pr+1], ah[mt][0],ah[mt][1],ah[mt][2],ah[mt][3], bh2,bh3);
                    mma_bf16(acc[mt][2*pr+1], ah[mt][0],ah[mt][1],ah[mt][2],ah[mt][3], bl2,bl3);
                    mma_bf16(acc[mt][2*pr+1], al[mt][0],al[mt][1],al[mt][2],al[mt][3], bh2,bh3);
                }
            }
        }

        #pragma unroll
        for (int mt = 0; mt < 2; mt++) {
            #pragma unroll
            for (int half = 0; half < 2; half++) {
                int prow = rowBase + mr + mt*16 + half*8 + g;
                int b = prow / 6016; int rem = prow % 6016;
                int hp = 1 + rem / 1504; int wp = rem % 1504;
                size_t orow = (size_t)(b*6 + hp)*1504 + wp;
                #pragma unroll
                for (int j = 0; j < 4; j++) {
                    int col = colBase + ncol + j*8 + tg*2;
                    float2 v = half ? make_float2(acc[mt][j].z, acc[mt][j].w)
                                    : make_float2(acc[mt][j].x, acc[mt][j].y);
                    *(float2*)&d_qk1[orow*256 + col] = v;
                }
            }
        }
    } else {
        int vcolBase = (blockIdx.y - 4) * 128;
        int ncol = (wid & 1) * 64;

        __half* Af = (__half*)sh;
        __half* Bf = Af + 128*72;

        {
            int r = tid >> 1;
            int half = (tid & 1) * 32;
            int prow = rowBase + r;
            int b = prow / 6016; int rem = prow % 6016;
            int hp = 1 + rem / 1504; int wp = rem % 1504;
            bool valid = (wp >= 2 && wp < 1502);
            __half* df = Af + r*72 + half;
            if (valid) {
                int pos = ((b*4 + (hp-1))*1500 + (wp-2))*64 + half;
                const uint4* sF = (const uint4*)(d_h1f + pos);
                #pragma unroll
                for (int u = 0; u < 4; u++) ((uint4*)df)[u] = sF[u];
            } else {
                uint4 z = make_uint4(0,0,0,0);
                #pragma unroll
                for (int u = 0; u < 4; u++) ((uint4*)df)[u] = z;
            }
        }
        {
            int n = tid >> 1;
            int seg = (tid & 1) * 32;
            const uint4* sF = (const uint4*)(d_W1f + (vcolBase + n)*64 + seg);
            uint4* df = (uint4*)(Bf + n*72 + seg);
            #pragma unroll
            for (int u = 0; u < 4; u++) df[u] = sF[u];
        }
        __syncthreads();

        uint32_t aAddr[2];
        #pragma unroll
        for (int mt = 0; mt < 2; mt++)
            aAddr[mt] = (uint32_t)__cvta_generic_to_shared(Af + (mr + mt*16 + arow)*72 + acol);
        uint32_t bAddr[4];
        #pragma unroll
        for (int pr = 0; pr < 4; pr++)
            bAddr[pr] = (uint32_t)__cvta_generic_to_shared(Bf + (ncol + pr*16 + brow)*72 + bcol);

        float4 acc[2][8];
        #pragma unroll
        for (int i = 0; i < 2; i++)
            #pragma unroll
            for (int j = 0; j < 8; j++) acc[i][j] = make_float4(0.f,0.f,0.f,0.f);

        #pragma unroll
        for (int ks = 0; ks < 4; ks++) {
            uint32_t koff = ks * 32;
            uint32_t af[2][4];
            #pragma unroll
            for (int mt = 0; mt < 2; mt++)
                ldsm_x4(af[mt][0],af[mt][1],af[mt][2],af[mt][3], aAddr[mt] + koff);
            #pragma unroll
            for (int pr = 0; pr < 4; pr++) {
                uint32_t b0,b1,b2,b3;
                ldsm_x4(b0,b1,b2,b3, bAddr[pr] + koff);
                #pragma unroll
                for (int mt = 0; mt < 2; mt++) {
                    mma_fp16(acc[mt][2*pr  ], af[mt][0],af[mt][1],af[mt][2],af[mt][3], b0,b1);
                    mma_fp16(acc[mt][2*pr+1], af[mt][0],af[mt][1],af[mt][2],af[mt][3], b2,b3);
                }
            }
        }

        #pragma unroll
        for (int mt = 0; mt < 2; mt++) {
            #pragma unroll
            for (int half = 0; half < 2; half++) {
                int prow = rowBase + mr + mt*16 + half*8 + g;
                int b = prow / 6016; int rem = prow % 6016;
                int hp = 1 + rem / 1504; int wp = rem % 1504;
                size_t orow = (size_t)(b*6 + hp)*1504 + wp;
                #pragma unroll
                for (int j = 0; j < 8; j++) {
                    int col = vcolBase + ncol + j*8 + tg*2;
                    float2 v = half ? make_float2(acc[mt][j].z, acc[mt][j].w)
                                    : make_float2(acc[mt][j].x, acc[mt][j].y);
                    __half2 hv;
                    hv.x = __float2half_rn(v.x);
                    hv.y = __float2half_rn(v.y);
                    *(__half2*)&d_v1[orow*512 + col] = hv;
                }
            }
        }
    }
}

// ---------------------------------------------------------------------------
// K5: stage1 attention combine, 25 positions/block, 512 threads.
// grid (60, 4, 2). kv window rows jj in [0,29) per i (w0+28 <= 1503).
// smem: sq[25][128]f + sk[58][128]f + sv[58][512]h = 101888 B
// ---------------------------------------------------------------------------
#define K5_SMEM ((25*128 + 58*128) * 4 + 58*512*2)

__global__ void k5_attn1()
{
    extern __shared__ float sm5[];
    float* sq = sm5;                               // [25][128]
    float* sk = sm5 + 25*128;                      // [58][128] r=i*29+jj
    __half* sv = (__half*)(sm5 + 25*128 + 58*128); // [58][512]

    int w0 = blockIdx.x * 25, h = blockIdx.y, b = blockIdx.z;
    int tid = threadIdx.x, lane = tid & 31, wrp = tid >> 5;  // 16 warps
    __shared__ float ssc[25][10];
    __shared__ float cm4[25][40];

    const float* qkbase = d_qk1 + (size_t)b * 6 * 1504 * 256;
    const __half* vbase = d_v1 + (size_t)b * 6 * 1504 * 512;

    // stage q: 25 rows x 32 float4 = 800
    for (int idx = tid; idx < 800; idx += 512) {
        int p = idx >> 5, c4 = idx & 31;
        ((float4*)sq)[p*32 + c4] =
            *(const float4*)(qkbase + ((h+1)*1504 + (w0+2+p))*256 + c4*4);
    }
    // stage k: 58 rows x 32 float4 = 1856
    for (int idx = tid; idx < 1856; idx += 512) {
        int r = idx >> 5, c4 = idx & 31;
        int i = r / 29, jj = r % 29;
        ((float4*)(sk + r*128))[c4] =
            *(const float4*)(qkbase + ((h+i)*1504 + (w0+jj))*256 + 128 + c4*4);
    }
    // stage v: 58 rows x 64 uint4 = 3712
    for (int idx = tid; idx < 3712; idx += 512) {
        int r = idx >> 6, c4 = idx & 63;
        int i = r / 29, jj = r % 29;
        ((uint4*)(sv + r*512))[c4] =
            *(const uint4*)(vbase + ((h+i)*1504 + (w0+jj))*512 + c4*8);
    }
    __syncthreads();

    // scores: 250 (p,kl) pairs over 16 warps
    for (int pair = wrp; pair < 250; pair += 16) {
        int p = pair / 10, kl = pair % 10;
        int i = kl / 5, j = kl % 5;
        float4 q4 = ((const float4*)(sq + p*128))[lane];
        float4 k4 = ((const float4*)(sk + (i*29 + p + j)*128))[lane];
        float s = q4.x*k4.x + q4.y*k4.y + q4.z*k4.z + q4.w*k4.w;
        #pragma unroll
        for (int off = 16; off; off >>= 1) s += __shfl_xor_sync(0xffffffffu, s, off);
        if (lane == 0) ssc[p][kl] = s;
    }
    __syncthreads();
    if (tid < 25) {
        float mx = -1e30f;
        #pragma unroll
        for (int kl = 0; kl < 10; kl++) mx = fmaxf(mx, ssc[tid][kl]);
        float e[10], s = 0.f;
        #pragma unroll
        for (int kl = 0; kl < 10; kl++) { e[kl] = __expf(ssc[tid][kl]-mx); s += e[kl]; }
        float inv = 1.f / s;
        #pragma unroll
        for (int kl = 0; kl < 10; kl++) {
            float a = e[kl] * inv;
            #pragma unroll
            for (int m = 0; m < 4; m++) cm4[tid][kl*4+m] = a * d_emb1[m*10+kl];
        }
    }
    __syncthreads();

    int o = tid & 127;
    int ph = tid >> 7;    // 0..3
    float s1 = 0.f, s2 = 0.f;
    for (int p = ph; p < 25; p += 4) {
        const float* cw = cm4[p];
        float acc = 0.f;
        #pragma unroll
        for (int kl = 0; kl < 10; kl++) {
            int i = kl / 5, j = kl % 5;
            uint2 pv = *(const uint2*)(sv + (i*29 + p + j)*512 + o*4);
            float2 v01 = __half22float2(*(const __half2*)&pv.x);
            float2 v23 = __half22float2(*(const __half2*)&pv.y);
            acc += cw[kl*4]*v01.x + cw[kl*4+1]*v01.y + cw[kl*4+2]*v23.x + cw[kl*4+3]*v23.y;
        }
        s1 += acc; s2 += acc*acc;
        if (!(h & 1) && !((w0+p) & 1))
            d_o1raw[((b*2 + (h>>1))*750 + ((w0+p)>>1))*128 + o] = acc;
    }
    atomicAdd(&P_SUM1[o], s1);
    atomicAdd(&P_SUMSQ1[o], s2);
}

// ---------------------------------------------------------------------------
// K8: stage2 qkv GEMM, ILP-split dots, 8 positions/block.
// grid (95, 2, 2), block 256.
// ---------------------------------------------------------------------------
#define K8_SMEM ((128*96 + 8*128) * 4)

__global__ void k8_gemm2(const float* g1, const float* b1)
{
    extern __shared__ float sm8[];
    float* sWt = sm8;               // [128][96]
    float* sa  = sm8 + 128*96;      // [8][128]
    __shared__ float sScale[128], sShift[128];

    int t = threadIdx.x;
    int hp = blockIdx.y, b = blockIdx.z;
    int W0 = blockIdx.x * 8;

    if (t < 128) {
        float n = 12000.f;
        float mean = P_SUM1[t] / n;
        float var  = P_SUMSQ1[t] / n - mean*mean;
        float sc = g1[t] * rsqrtf(var + 1e-5f);
        sScale[t] = sc;
        sShift[t] = b1[t] - mean*sc;
    }
    for (int idx = t; idx < 3072; idx += 256)
        ((float4*)sWt)[idx] = ((const float4*)d_Wcat2)[idx];
    __syncthreads();

    for (int idx = t; idx < 1024; idx += 256) {
        int ps = idx >> 7, i = idx & 127;
        int wp = W0 + ps;
        float v = 0.f;
        if (wp >= 2 && wp < 752) {
            float raw = d_o1raw[(((b*2 + hp)*750) + (wp-2))*128 + i];
            v = fmaxf(fmaf(raw, sScale[i], sShift[i]), 0.f);
        }
        sa[ps*128 + i] = v;
    }
    __syncthreads();

    #pragma unroll
    for (int k = 0; k < 3; k++) {
        int pair = t + k*256;
        int ps = pair / 96, o = pair - (pair/96)*96;
        int wp = W0 + ps;
        if (wp >= 754) continue;
        const float* av = sa + ps*128;
        float a0 = 0.f, a1 = 0.f, a2 = 0.f, a3 = 0.f;
        #pragma unroll
        for (int c = 0; c < 32; c++) {
            a0 = fmaf(av[c],     sWt[c*96 + o],        a0);
            a1 = fmaf(av[c+32],  sWt[(c+32)*96 + o],   a1);
            a2 = fmaf(av[c+64],  sWt[(c+64)*96 + o],   a2);
            a3 = fmaf(av[c+96],  sWt[(c+96)*96 + o],   a3);
        }
        d_qkv2[(((b*2 + hp)*754) + wp)*96 + o] = (a0 + a1) + (a2 + a3);
    }
}

// ---------------------------------------------------------------------------
// K9: stage2 attention combine, warp per position. grid (188, 2), block 128
// ---------------------------------------------------------------------------
__global__ void k9_attn2()
{
    __shared__ float semb[40];
    int tid = threadIdx.x;
    if (tid < 40) { int kl = tid >> 2, m = tid & 3; semb[tid] = d_emb2[m*10+kl]; }
    __syncthreads();

    int lane = tid & 31, wrp = tid >> 5;
    int w = blockIdx.x * 4 + wrp, b = blockIdx.y;
    if (w >= 750) return;

    const float* base = d_qkv2 + (size_t)b * 2 * 754 * 96;
    const float* qp = base + (w + 2) * 96;
    float qv = (lane < 16) ? qp[lane] : 0.f;

    float scl[10];
    float mx = -1e30f;
    #pragma unroll
    for (int kl = 0; kl < 10; kl++) {
        int i = kl / 5, j = kl % 5;
        const float* kp = base + (i*754 + (w+j))*96 + 16;
        float pr = (lane < 16) ? qv * kp[lane] : 0.f;
        #pragma unroll
        for (int off = 8; off; off >>= 1) pr += __shfl_xor_sync(0xffffffffu, pr, off);
        scl[kl] = pr;
        mx = fmaxf(mx, pr);
    }
    float s = 0.f;
    #pragma unroll
    for (int kl = 0; kl < 10; kl++) { scl[kl] = __expf(scl[kl]-mx); s += scl[kl]; }
    float inv = 1.f / s;
    if (lane < 16) {
        float acc = 0.f;
        #pragma unroll
        for (int kl = 0; kl < 10; kl++) {
            int i = kl / 5, j = kl % 5;
            float4 v = *(const float4*)(base + (i*754 + (w+j))*96 + 32 + lane*4);
            float aw = scl[kl] * inv;
            acc += aw * (semb[kl*4]*v.x + semb[kl*4+1]*v.y + semb[kl*4+2]*v.z + semb[kl*4+3]*v.w);
        }
        d_out2[(b*750 + w)*16 + lane] = acc;
        atomicAdd(&P_SUM2[lane], acc);
        atomicAdd(&P_SUMSQ2[lane], acc*acc);
    }
}

// ---------------------------------------------------------------------------
// K11: stage2 BN + ReLU + AvgPool(1,56) -> out. grid (13,16,2), block 64
// ---------------------------------------------------------------------------
__global__ void k11_final(float* out, const float* g2, const float* b2)
{
    int n = blockIdx.x, c = blockIdx.y, b = blockIdx.z;
    int t = threadIdx.x;
    float nn = 1500.f;
    float mean = P_SUM2[c] / nn;
    float var  = P_SUMSQ2[c] / nn - mean*mean;
    float sc = g2[c] * rsqrtf(var + 1e-5f);
    float sf = b2[c] - mean * sc;

    float v = 0.f;
    if (t < 56) {
        float raw = d_out2[(b*750 + n*56 + t)*16 + c];
        v = fmaxf(fmaf(raw, sc, sf), 0.f);
    }
    __shared__ float shm[64];
    shm[t] = v;
    __syncthreads();
    for (int st = 32; st; st >>= 1) {
        if (t < st) shm[t] += shm[t+st];
        __syncthreads();
    }
    if (t == 0) out[(b*16 + c)*13 + n] = shm[0] * (1.f/56.f);
}

// ---------------------------------------------------------------------------
extern "C" void kernel_launch(void* const* d_in, const int* in_sizes, int n_in,
                              void* d_out, int out_size)
{
    const float* x     = (const float*)d_in[0];
    const float* p0_q  = (const float*)d_in[1];
    const float* p0_k  = (const float*)d_in[2];
    const float* p0_v  = (const float*)d_in[3];
    const float* p0_ea = (const float*)d_in[4];
    const float* p0_eb = (const float*)d_in[5];
    const float* p0_em = (const float*)d_in[6];
    const float* p0_g  = (const float*)d_in[7];
    const float* p0_b  = (const float*)d_in[8];
    const float* p1_q  = (const float*)d_in[9];
    const float* p1_k  = (const float*)d_in[10];
    const float* p1_v  = (const float*)d_in[11];
    const float* p1_ea = (const float*)d_in[12];
    const float* p1_eb = (const float*)d_in[13];
    const float* p1_em = (const float*)d_in[14];
    const float* p1_g  = (const float*)d_in[15];
    const float* p1_b  = (const float*)d_in[16];
    const float* p2_q  = (const float*)d_in[17];
    const float* p2_k  = (const float*)d_in[18];
    const float* p2_v  = (const float*)d_in[19];
    const float* p2_ea = (const float*)d_in[20];
    const float* p2_eb = (const float*)d_in[21];
    const float* p2_em = (const float*)d_in[22];
    const float* p2_g  = (const float*)d_in[23];
    const float* p2_b  = (const float*)d_in[24];
    float* out = (float*)d_out;

    static int smem_set = 0;
    if (!smem_set) {
        cudaFuncSetAttribute(k4_gemm1, cudaFuncAttributeMaxDynamicSharedMemorySize, K4_SMEM);
        cudaFuncSetAttribute(k4_gemm1, cudaFuncAttributePreferredSharedMemoryCarveout,
                             cudaSharedmemCarveoutMaxShared);
        cudaFuncSetAttribute(k5_attn1, cudaFuncAttributeMaxDynamicSharedMemorySize, K5_SMEM);
        cudaFuncSetAttribute(k5_attn1, cudaFuncAttributePreferredSharedMemoryCarveout,
                             cudaSharedmemCarveoutMaxShared);
        cudaFuncSetAttribute(k8_gemm2, cudaFuncAttributeMaxDynamicSharedMemorySize, K8_SMEM);
        smem_set = 1;
    }

    k0_pre<<<17, 256>>>(p0_q, p0_k, p0_v, p0_ea, p0_eb, p0_em,
                        p1_q, p1_k, p1_v, p1_ea, p1_eb, p1_em,
                        p2_q, p2_k, p2_v, p2_ea, p2_eb, p2_em);
    k1_stem0<<<dim3(24, 8, 2), 128>>>(x);
    k3_h1<<<3000, 256>>>(p0_g, p0_b);
    k4_gemm1<<<dim3(94, 8), 256, K4_SMEM>>>();
    k5_attn1<<<dim3(60, 4, 2), 512, K5_SMEM>>>();
    k8_gemm2<<<dim3(95, 2, 2), 256, K8_SMEM>>>(p1_g, p1_b);
    k9_attn2<<<dim3(188, 2), 128>>>();
    k11_final<<<dim3(13, 16, 2), 64>>>(out, p2_g, p2_b);
}